// round 11
// baseline (speedup 1.0000x reference)
#include <cuda_runtime.h>
#include <cuda_bf16.h>
#include <cstdint>
#include <math.h>

// ===========================================================================
// out = softmax((xWq+bq)(xWk+bk)^T / 32) (xWv+bv);  B=4, S=2048, D=H=1024
// tf32 mma.sync GEMMs, operands pre-rounded to tf32 (zero cvt in mainloop),
// LDS.64 fragment loads via k-slot remap + XOR-swizzled 128B-row tiles,
// 64x64 warp tiles, A+B fragments double-buffered across kk.
// This round: 128x256 CTA tiles (256 thr, 2x4 warps, 1 CTA/SM) — halves
// barrier frequency and crossbar traffic per MAC; same 8 warps/SM.
// ===========================================================================

#define BATCH 4
#define SEQ   2048
#define DIM   1024

__device__ float g_Q [BATCH * SEQ * DIM];
__device__ float g_K [BATCH * SEQ * DIM];
__device__ float g_V [BATCH * SEQ * DIM];
__device__ float g_S [BATCH * SEQ * SEQ];
__device__ float g_xr[BATCH * SEQ * DIM];    // x rounded; reused as V^T later
__device__ float g_Wt[3 * DIM * DIM];        // packed W^T: rows n(3072), cols k(1024)
__device__ float g_b [3 * DIM];              // packed bq|bk|bv

// ---------------- helpers ---------------------------------------------------
__device__ __forceinline__ uint32_t smem_u32(const void* p) {
    uint32_t a;
    asm("{ .reg .u64 t; cvta.to.shared.u64 t, %1; cvt.u32.u64 %0, t; }"
        : "=r"(a) : "l"(p));
    return a;
}
__device__ __forceinline__ void cp16(uint32_t saddr, const void* g) {
    asm volatile("cp.async.cg.shared.global [%0], [%1], 16;" :: "r"(saddr), "l"(g));
}
__device__ __forceinline__ float round_tf32(float x) {
    uint32_t r;
    asm("cvt.rna.tf32.f32 %0, %1;" : "=r"(r) : "f"(x));
    return __uint_as_float(r);
}
__device__ __forceinline__ void mma_tf32(float* c, const uint32_t* a, const uint32_t* b) {
    asm volatile(
        "mma.sync.aligned.m16n8k8.row.col.f32.tf32.tf32.f32 "
        "{%0,%1,%2,%3}, {%4,%5,%6,%7}, {%8,%9}, {%0,%1,%2,%3};"
        : "+f"(c[0]), "+f"(c[1]), "+f"(c[2]), "+f"(c[3])
        : "r"(a[0]), "r"(a[1]), "r"(a[2]), "r"(a[3]), "r"(b[0]), "r"(b[1]));
}

// ===========================================================================
// NT GEMM: C[M,N] = A[M,K] x B[N,K]^T, 128x256xKB32 CTA tiles, 256 threads,
// 8 warps as 2(m)x4(n) with 64x64 warp tiles. 3-stage cp.async, XOR-swizzled
// 128B-row tiles, A+B fragments double-buffered across kk (ping-pong).
// MODE: 1 = *alpha, 2 = plain, 3 = fused QKV (+packed bias, tf32 round,
//       route to C0/C1/C2 by n0>>10)
// ===========================================================================
#define TM 128
#define TN 256
#define KB 32
#define ASTRIDE (TM * 32)                   // 4096 floats / stage
#define BSTRIDE (TN * 32)                   // 8192 floats / stage
#define GSMEM   (3 * (ASTRIDE + BSTRIDE) * 4)   // 147456 B

template <int MODE>
__global__ __launch_bounds__(256, 1)
void gemm_nt(const float* __restrict__ Abase, const float* __restrict__ Bbase,
             const float* __restrict__ bias,
             float* __restrict__ C0, float* __restrict__ C1, float* __restrict__ C2,
             int M, int N, int K, int ldc,
             long long sA, long long sB, long long sC, float alpha)
{
    extern __shared__ float sm[];
    const int tid  = threadIdx.x;
    const int wid  = tid >> 5;
    const int lane = tid & 31;
    const int gq = lane >> 2;
    const int tq = lane & 3;
    const int wm = (wid >> 2) * 64;     // 2(m) x 4(n) warp grid, 64x64 tiles
    const int wn = (wid & 3) * 64;
    const int axk = (gq & 3) << 2;

    const float* A = Abase + (long long)blockIdx.z * sA;
    const float* B = Bbase + (long long)blockIdx.z * sB;
    const int m0 = blockIdx.y * TM;
    const int n0 = blockIdx.x * TN;

    float* As = sm;
    float* Bs = sm + 3 * ASTRIDE;

    auto loadA = [&](int k0, int s) {
        float* dst = As + s * ASTRIDE;
        const float* src = A + (long long)m0 * K + k0;
#pragma unroll
        for (int j = 0; j < 4; j++) {                 // 128 rows x 8 chunks
            int idx = j * 256 + tid;
            int r = idx >> 3, ch = idx & 7;
            int off = r * 32 + (((2 * ch) ^ ((r & 3) << 2)) << 1);
            cp16(smem_u32(dst + off), src + (long long)r * K + ch * 4);
        }
    };
    auto loadB = [&](int k0, int s) {
        float* dst = Bs + s * BSTRIDE;
        const float* src = B + (long long)n0 * K + k0;
#pragma unroll
        for (int j = 0; j < 8; j++) {                 // 256 rows x 8 chunks
            int idx = j * 256 + tid;
            int r = idx >> 3, ch = idx & 7;
            int off = r * 32 + (((2 * ch) ^ ((r & 3) << 2)) << 1);
            cp16(smem_u32(dst + off), src + (long long)r * K + ch * 4);
        }
    };

    float acc[4][8][4] = {};

    const int nIter = K / KB;
    loadA(0, 0); loadB(0, 0);
    asm volatile("cp.async.commit_group;" ::: "memory");
    loadA(KB, 1); loadB(KB, 1);
    asm volatile("cp.async.commit_group;" ::: "memory");

    for (int it = 0; it < nIter; it++) {
        asm volatile("cp.async.wait_group 1;" ::: "memory");
        __syncthreads();

        if (it + 2 < nIter) {
            loadA((it + 2) * KB, (it + 2) % 3);
            loadB((it + 2) * KB, (it + 2) % 3);
        }
        asm volatile("cp.async.commit_group;" ::: "memory");

        const float* a_s = As + (it % 3) * ASTRIDE;
        const float* b_s = Bs + (it % 3) * BSTRIDE;

        uint32_t af[2][4][4];
        uint32_t bf[2][8][2];
        auto ldfrag = [&](int kk, uint32_t (&afx)[4][4], uint32_t (&bfx)[8][2]) {
            const int cA = (((kk << 2) + tq) ^ axk) << 1;
#pragma unroll
            for (int i = 0; i < 4; i++) {
                const float* ap = a_s + (wm + i * 16 + gq) * 32 + cA;
                uint2 u0 = *reinterpret_cast<const uint2*>(ap);
                uint2 u1 = *reinterpret_cast<const uint2*>(ap + 8 * 32);
                afx[i][0] = u0.x; afx[i][1] = u1.x;
                afx[i][2] = u0.y; afx[i][3] = u1.y;
            }
#pragma unroll
            for (int j = 0; j < 8; j++) {
                const float* bp = b_s + (wn + j * 8 + gq) * 32 + cA;
                uint2 v = *reinterpret_cast<const uint2*>(bp);
                bfx[j][0] = v.x; bfx[j][1] = v.y;
            }
        };

        ldfrag(0, af[0], bf[0]);
#pragma unroll
        for (int kk = 0; kk < 4; kk++) {
            if (kk < 3) ldfrag(kk + 1, af[(kk + 1) & 1], bf[(kk + 1) & 1]);
#pragma unroll
            for (int i = 0; i < 4; i++)
#pragma unroll
                for (int j = 0; j < 8; j++)
                    mma_tf32(acc[i][j], af[kk & 1][i], bf[kk & 1][j]);
        }
    }

    // epilogue
    float* Cw;
    int cshift = 0;
    if (MODE == 3) {
        const int mat = n0 >> 10;           // TN=256 divides 1024: tile stays in one matrix
        Cw = (mat == 0) ? C0 : (mat == 1) ? C1 : C2;
        cshift = n0 & ~1023;
    } else {
        Cw = C0 + (long long)blockIdx.z * sC;
    }
#pragma unroll
    for (int i = 0; i < 4; i++) {
#pragma unroll
        for (int j = 0; j < 8; j++) {
            const int r = m0 + wm + i * 16 + gq;
            const int c = n0 + wn + j * 8 + 2 * tq;
            float2 v0 = make_float2(acc[i][j][0], acc[i][j][1]);
            float2 v1 = make_float2(acc[i][j][2], acc[i][j][3]);
            if (MODE == 3) {
                float2 bz2 = *reinterpret_cast<const float2*>(bias + c);
                v0.x = round_tf32(v0.x + bz2.x);
                v0.y = round_tf32(v0.y + bz2.y);
                v1.x = round_tf32(v1.x + bz2.x);
                v1.y = round_tf32(v1.y + bz2.y);
            }
            if (MODE == 1) {
                v0.x *= alpha; v0.y *= alpha;
                v1.x *= alpha; v1.y *= alpha;
            }
            const int cc = c - cshift;
            *reinterpret_cast<float2*>(Cw + (long long)r * ldc + cc) = v0;
            *reinterpret_cast<float2*>(Cw + (long long)(r + 8) * ldc + cc) = v1;
        }
    }
}

// ---------------------------------------------------------------------------
// tf32 rounding + transpose utilities
// ---------------------------------------------------------------------------
__global__ __launch_bounds__(256)
void round_pass(const float* __restrict__ src, float* __restrict__ dst)
{
    int idx = blockIdx.x * 256 + threadIdx.x;
    float4 v = reinterpret_cast<const float4*>(src)[idx];
    v.x = round_tf32(v.x); v.y = round_tf32(v.y);
    v.z = round_tf32(v.z); v.w = round_tf32(v.w);
    reinterpret_cast<float4*>(dst)[idx] = v;
}

// transpose+round all three W [1024,1024] into packed W^T [3072,1024];
// blockIdx.z selects the source weight matrix.
__global__ void transp_w3(const float* __restrict__ w0, const float* __restrict__ w1,
                          const float* __restrict__ w2, float* __restrict__ out)
{
    __shared__ float t[32][33];
    const float* in = (blockIdx.z == 0) ? w0 : (blockIdx.z == 1) ? w1 : w2;
    float* o = out + (long long)blockIdx.z * DIM * DIM;
    int r0 = blockIdx.y * 32, c0 = blockIdx.x * 32;
    int tx = threadIdx.x, ty = threadIdx.y;
#pragma unroll
    for (int i = 0; i < 4; i++)
        t[ty + i * 8][tx] = in[(long long)(r0 + ty + i * 8) * DIM + c0 + tx];
    __syncthreads();
#pragma unroll
    for (int i = 0; i < 4; i++) {
        int oc = ty + i * 8;
        o[(long long)(c0 + oc) * DIM + r0 + tx] = round_tf32(t[tx][oc]);
    }
}

// transpose V per batch: [2048,1024] -> [1024,2048]
__global__ void transp_v(const float* __restrict__ in, float* __restrict__ out)
{
    __shared__ float t[32][33];
    in  += (long long)blockIdx.z * SEQ * DIM;
    out += (long long)blockIdx.z * DIM * SEQ;
    int r0 = blockIdx.y * 32, c0 = blockIdx.x * 32;
    int tx = threadIdx.x, ty = threadIdx.y;
#pragma unroll
    for (int i = 0; i < 4; i++)
        t[ty + i * 8][tx] = in[(long long)(r0 + ty + i * 8) * DIM + c0 + tx];
    __syncthreads();
#pragma unroll
    for (int i = 0; i < 4; i++) {
        int oc = ty + i * 8;
        out[(long long)(c0 + oc) * SEQ + r0 + tx] = t[tx][oc];
    }
}

__global__ void pack_bias(const float* __restrict__ b0, const float* __restrict__ b1,
                          const float* __restrict__ b2, float* __restrict__ dst)
{
    int t = threadIdx.x + blockIdx.x * 1024;
    const float* s = (blockIdx.x == 0) ? b0 : (blockIdx.x == 1) ? b1 : b2;
    dst[t] = s[threadIdx.x];
}

// ---------------------------------------------------------------------------
// Row softmax (rows of 2048), 256 threads, warp-shuffle reduce, tf32 out.
// ---------------------------------------------------------------------------
__global__ __launch_bounds__(256)
void softmax_rows(float* __restrict__ S)
{
    float4* row4 = reinterpret_cast<float4*>(S + (long long)blockIdx.x * SEQ);
    __shared__ float red[8];
    const int t = threadIdx.x;
    const int wid = t >> 5, lane = t & 31;

    float4 a = row4[t];
    float4 b = row4[t + 256];
    float mx = fmaxf(fmaxf(fmaxf(a.x, a.y), fmaxf(a.z, a.w)),
                     fmaxf(fmaxf(b.x, b.y), fmaxf(b.z, b.w)));
#pragma unroll
    for (int s = 16; s > 0; s >>= 1)
        mx = fmaxf(mx, __shfl_xor_sync(0xffffffffu, mx, s));
    if (lane == 0) red[wid] = mx;
    __syncthreads();
    mx = red[0];
#pragma unroll
    for (int i = 1; i < 8; i++) mx = fmaxf(mx, red[i]);

    a.x = __expf(a.x - mx); a.y = __expf(a.y - mx);
    a.z = __expf(a.z - mx); a.w = __expf(a.w - mx);
    b.x = __expf(b.x - mx); b.y = __expf(b.y - mx);
    b.z = __expf(b.z - mx); b.w = __expf(b.w - mx);
    float sum = (a.x + a.y) + (a.z + a.w) + (b.x + b.y) + (b.z + b.w);
#pragma unroll
    for (int s = 16; s > 0; s >>= 1)
        sum += __shfl_xor_sync(0xffffffffu, sum, s);
    __syncthreads();
    if (lane == 0) red[wid] = sum;
    __syncthreads();
    sum = red[0];
#pragma unroll
    for (int i = 1; i < 8; i++) sum += red[i];
    float inv = 1.0f / sum;

    a.x = round_tf32(a.x * inv); a.y = round_tf32(a.y * inv);
    a.z = round_tf32(a.z * inv); a.w = round_tf32(a.w * inv);
    b.x = round_tf32(b.x * inv); b.y = round_tf32(b.y * inv);
    b.z = round_tf32(b.z * inv); b.w = round_tf32(b.w * inv);
    row4[t] = a;
    row4[t + 256] = b;
}

// ---------------------------------------------------------------------------
extern "C" void kernel_launch(void* const* d_in, const int* in_sizes, int n_in,
                              void* d_out, int out_size)
{
    const float* x  = (const float*)d_in[0];
    const float* Wq = (const float*)d_in[1];
    const float* bq = (const float*)d_in[2];
    const float* Wk = (const float*)d_in[3];
    const float* bk = (const float*)d_in[4];
    const float* Wv = (const float*)d_in[5];
    const float* bv = (const float*)d_in[6];
    float* out = (float*)d_out;

    static float *pQ = nullptr, *pK = nullptr, *pV = nullptr, *pS = nullptr,
                 *pxr = nullptr, *pWt = nullptr, *pb = nullptr;
    if (!pQ) {
        cudaGetSymbolAddress((void**)&pQ,  g_Q);
        cudaGetSymbolAddress((void**)&pK,  g_K);
        cudaGetSymbolAddress((void**)&pV,  g_V);
        cudaGetSymbolAddress((void**)&pS,  g_S);
        cudaGetSymbolAddress((void**)&pxr, g_xr);
        cudaGetSymbolAddress((void**)&pWt, g_Wt);
        cudaGetSymbolAddress((void**)&pb,  g_b);
        cudaFuncSetAttribute(gemm_nt<3>, cudaFuncAttributeMaxDynamicSharedMemorySize, GSMEM);
        cudaFuncSetAttribute(gemm_nt<1>, cudaFuncAttributeMaxDynamicSharedMemorySize, GSMEM);
        cudaFuncSetAttribute(gemm_nt<2>, cudaFuncAttributeMaxDynamicSharedMemorySize, GSMEM);
    }

    const int M = BATCH * SEQ;          // 8192
    const float scale = 0.03125f;       // 1/sqrt(1024)
    dim3 tb(32, 8);

    // 0) pre-round x; W^T packed+rounded (single z=3 launch); bias packed
    round_pass<<<M * DIM / 1024, 256>>>(x, pxr);
    transp_w3<<<dim3(32, 32, 3), tb>>>(Wq, Wk, Wv, pWt);
    pack_bias<<<3, 1024>>>(bq, bk, bv, pb);

    // 1) fused QKV projection: [8192,1024] x W^T[3072,1024] -> Q,K,V
    gemm_nt<3><<<dim3(3072 / TN, M / TM, 1), 256, GSMEM>>>(
        pxr, pWt, pb, pQ, pK, pV, M, 3072, DIM, DIM, 0, 0, 0, 1.f);

    // 1b) V^T per batch: [2048,1024] -> [1024,2048]  (into pxr, now free)
    transp_v<<<dim3(32, 64, BATCH), tb>>>(pV, pxr);

    // 2) scores = Q K^T * scale (per batch, NT)
    gemm_nt<1><<<dim3(SEQ / TN, SEQ / TM, BATCH), 256, GSMEM>>>(
        pQ, pK, nullptr, pS, nullptr, nullptr,
        SEQ, SEQ, DIM, SEQ,
        (long long)SEQ * DIM, (long long)SEQ * DIM, (long long)SEQ * SEQ, scale);

    // 3) softmax rows (in place, tf32-rounded)
    softmax_rows<<<BATCH * SEQ, 256>>>(pS);

    // 4) out = P V  = P x (V^T)^T (per batch, NT)
    gemm_nt<2><<<dim3(DIM / TN, SEQ / TM, BATCH), 256, GSMEM>>>(
        pS, pxr, nullptr, out, nullptr, nullptr,
        SEQ, DIM, SEQ, DIM,
        (long long)SEQ * SEQ, (long long)DIM * SEQ, (long long)SEQ * DIM, 1.f);
}

// round 12
// speedup vs baseline: 1.1663x; 1.1663x over previous
#include <cuda_runtime.h>
#include <cuda_bf16.h>
#include <cstdint>
#include <math.h>

// ===========================================================================
// out = softmax((xWq+bq)(xWk+bk)^T / 32) (xWv+bv);  B=4, S=2048, D=H=1024
// tf32 mma.sync GEMMs (R10 config: 128x128 CTA tiles, 128 thr, 2 CTAs/SM,
// 64x64 warp tiles, A+B fragment ping-pong, XOR-swizzled tiles).
// This round: multi-stream graph — parallel pre-passes, per-batch
// score->softmax->PV pipeline across 4 streams (softmax+tails hidden).
// ===========================================================================

#define BATCH 4
#define SEQ   2048
#define DIM   1024

__device__ float g_Q [BATCH * SEQ * DIM];
__device__ float g_K [BATCH * SEQ * DIM];
__device__ float g_V [BATCH * SEQ * DIM];
__device__ float g_S [BATCH * SEQ * SEQ];
__device__ float g_xr[BATCH * SEQ * DIM];    // x rounded; reused as V^T later
__device__ float g_Wt[3 * DIM * DIM];        // packed W^T: rows n(3072), cols k(1024)
__device__ float g_b [3 * DIM];              // packed bq|bk|bv

// ---------------- helpers ---------------------------------------------------
__device__ __forceinline__ uint32_t smem_u32(const void* p) {
    uint32_t a;
    asm("{ .reg .u64 t; cvta.to.shared.u64 t, %1; cvt.u32.u64 %0, t; }"
        : "=r"(a) : "l"(p));
    return a;
}
__device__ __forceinline__ void cp16(uint32_t saddr, const void* g) {
    asm volatile("cp.async.cg.shared.global [%0], [%1], 16;" :: "r"(saddr), "l"(g));
}
__device__ __forceinline__ float round_tf32(float x) {
    uint32_t r;
    asm("cvt.rna.tf32.f32 %0, %1;" : "=r"(r) : "f"(x));
    return __uint_as_float(r);
}
__device__ __forceinline__ void mma_tf32(float* c, const uint32_t* a, const uint32_t* b) {
    asm volatile(
        "mma.sync.aligned.m16n8k8.row.col.f32.tf32.tf32.f32 "
        "{%0,%1,%2,%3}, {%4,%5,%6,%7}, {%8,%9}, {%0,%1,%2,%3};"
        : "+f"(c[0]), "+f"(c[1]), "+f"(c[2]), "+f"(c[3])
        : "r"(a[0]), "r"(a[1]), "r"(a[2]), "r"(a[3]), "r"(b[0]), "r"(b[1]));
}

// ===========================================================================
// NT GEMM: C[M,N] = A[M,K] x B[N,K]^T, 128x128xKB32 CTA tiles, 128 threads,
// 4 warps as 2x2 with 64x64 warp tiles. 3-stage cp.async, XOR-swizzled
// 128B-row tiles, A+B fragments double-buffered across kk (ping-pong).
// MODE: 1 = *alpha, 2 = plain, 3 = fused QKV (+packed bias, tf32 round,
//       route to C0/C1/C2 by n0>>10)
// ===========================================================================
#define TM 128
#define TN 128
#define KB 32
#define ASTRIDE (TM * 32)
#define BSTRIDE (TN * 32)
#define GSMEM   (3 * (ASTRIDE + BSTRIDE) * 4)   // 98304 B

template <int MODE>
__global__ __launch_bounds__(128, 2)
void gemm_nt(const float* __restrict__ Abase, const float* __restrict__ Bbase,
             const float* __restrict__ bias,
             float* __restrict__ C0, float* __restrict__ C1, float* __restrict__ C2,
             int M, int N, int K, int ldc,
             long long sA, long long sB, long long sC, float alpha)
{
    extern __shared__ float sm[];
    const int tid  = threadIdx.x;
    const int wid  = tid >> 5;
    const int lane = tid & 31;
    const int gq = lane >> 2;
    const int tq = lane & 3;
    const int wm = (wid >> 1) * 64;     // 2x2 warp grid, 64x64 warp tiles
    const int wn = (wid & 1) * 64;
    const int axk = (gq & 3) << 2;

    const float* A = Abase + (long long)blockIdx.z * sA;
    const float* B = Bbase + (long long)blockIdx.z * sB;
    const int m0 = blockIdx.y * TM;
    const int n0 = blockIdx.x * TN;

    float* As = sm;
    float* Bs = sm + 3 * ASTRIDE;

    auto loadA = [&](int k0, int s) {
        float* dst = As + s * ASTRIDE;
        const float* src = A + (long long)m0 * K + k0;
#pragma unroll
        for (int j = 0; j < 8; j++) {
            int idx = j * 128 + tid;
            int r = idx >> 3, ch = idx & 7;
            int off = r * 32 + (((2 * ch) ^ ((r & 3) << 2)) << 1);
            cp16(smem_u32(dst + off), src + (long long)r * K + ch * 4);
        }
    };
    auto loadB = [&](int k0, int s) {
        float* dst = Bs + s * BSTRIDE;
        const float* src = B + (long long)n0 * K + k0;
#pragma unroll
        for (int j = 0; j < 8; j++) {
            int idx = j * 128 + tid;
            int r = idx >> 3, ch = idx & 7;
            int off = r * 32 + (((2 * ch) ^ ((r & 3) << 2)) << 1);
            cp16(smem_u32(dst + off), src + (long long)r * K + ch * 4);
        }
    };

    float acc[4][8][4] = {};

    const int nIter = K / KB;
    loadA(0, 0); loadB(0, 0);
    asm volatile("cp.async.commit_group;" ::: "memory");
    loadA(KB, 1); loadB(KB, 1);
    asm volatile("cp.async.commit_group;" ::: "memory");

    for (int it = 0; it < nIter; it++) {
        asm volatile("cp.async.wait_group 1;" ::: "memory");
        __syncthreads();

        if (it + 2 < nIter) {
            loadA((it + 2) * KB, (it + 2) % 3);
            loadB((it + 2) * KB, (it + 2) % 3);
        }
        asm volatile("cp.async.commit_group;" ::: "memory");

        const float* a_s = As + (it % 3) * ASTRIDE;
        const float* b_s = Bs + (it % 3) * BSTRIDE;

        uint32_t af[2][4][4];
        uint32_t bf[2][8][2];
        auto ldfrag = [&](int kk, uint32_t (&afx)[4][4], uint32_t (&bfx)[8][2]) {
            const int cA = (((kk << 2) + tq) ^ axk) << 1;
#pragma unroll
            for (int i = 0; i < 4; i++) {
                const float* ap = a_s + (wm + i * 16 + gq) * 32 + cA;
                uint2 u0 = *reinterpret_cast<const uint2*>(ap);
                uint2 u1 = *reinterpret_cast<const uint2*>(ap + 8 * 32);
                afx[i][0] = u0.x; afx[i][1] = u1.x;
                afx[i][2] = u0.y; afx[i][3] = u1.y;
            }
#pragma unroll
            for (int j = 0; j < 8; j++) {
                const float* bp = b_s + (wn + j * 8 + gq) * 32 + cA;
                uint2 v = *reinterpret_cast<const uint2*>(bp);
                bfx[j][0] = v.x; bfx[j][1] = v.y;
            }
        };

        ldfrag(0, af[0], bf[0]);
#pragma unroll
        for (int kk = 0; kk < 4; kk++) {
            if (kk < 3) ldfrag(kk + 1, af[(kk + 1) & 1], bf[(kk + 1) & 1]);
#pragma unroll
            for (int i = 0; i < 4; i++)
#pragma unroll
                for (int j = 0; j < 8; j++)
                    mma_tf32(acc[i][j], af[kk & 1][i], bf[kk & 1][j]);
        }
    }

    // epilogue
    float* Cw;
    int cshift = 0;
    if (MODE == 3) {
        const int mat = n0 >> 10;
        Cw = (mat == 0) ? C0 : (mat == 1) ? C1 : C2;
        cshift = n0 & ~1023;
    } else {
        Cw = C0 + (long long)blockIdx.z * sC;
    }
#pragma unroll
    for (int i = 0; i < 4; i++) {
#pragma unroll
        for (int j = 0; j < 8; j++) {
            const int r = m0 + wm + i * 16 + gq;
            const int c = n0 + wn + j * 8 + 2 * tq;
            float2 v0 = make_float2(acc[i][j][0], acc[i][j][1]);
            float2 v1 = make_float2(acc[i][j][2], acc[i][j][3]);
            if (MODE == 3) {
                float2 bz2 = *reinterpret_cast<const float2*>(bias + c);
                v0.x = round_tf32(v0.x + bz2.x);
                v0.y = round_tf32(v0.y + bz2.y);
                v1.x = round_tf32(v1.x + bz2.x);
                v1.y = round_tf32(v1.y + bz2.y);
            }
            if (MODE == 1) {
                v0.x *= alpha; v0.y *= alpha;
                v1.x *= alpha; v1.y *= alpha;
            }
            const int cc = c - cshift;
            *reinterpret_cast<float2*>(Cw + (long long)r * ldc + cc) = v0;
            *reinterpret_cast<float2*>(Cw + (long long)(r + 8) * ldc + cc) = v1;
        }
    }
}

// ---------------------------------------------------------------------------
// tf32 rounding + transpose utilities
// ---------------------------------------------------------------------------
__global__ __launch_bounds__(256)
void round_pass(const float* __restrict__ src, float* __restrict__ dst)
{
    int idx = blockIdx.x * 256 + threadIdx.x;
    float4 v = reinterpret_cast<const float4*>(src)[idx];
    v.x = round_tf32(v.x); v.y = round_tf32(v.y);
    v.z = round_tf32(v.z); v.w = round_tf32(v.w);
    reinterpret_cast<float4*>(dst)[idx] = v;
}

__global__ void transp_w3(const float* __restrict__ w0, const float* __restrict__ w1,
                          const float* __restrict__ w2, float* __restrict__ out)
{
    __shared__ float t[32][33];
    const float* in = (blockIdx.z == 0) ? w0 : (blockIdx.z == 1) ? w1 : w2;
    float* o = out + (long long)blockIdx.z * DIM * DIM;
    int r0 = blockIdx.y * 32, c0 = blockIdx.x * 32;
    int tx = threadIdx.x, ty = threadIdx.y;
#pragma unroll
    for (int i = 0; i < 4; i++)
        t[ty + i * 8][tx] = in[(long long)(r0 + ty + i * 8) * DIM + c0 + tx];
    __syncthreads();
#pragma unroll
    for (int i = 0; i < 4; i++) {
        int oc = ty + i * 8;
        o[(long long)(c0 + oc) * DIM + r0 + tx] = round_tf32(t[tx][oc]);
    }
}

__global__ void transp_v(const float* __restrict__ in, float* __restrict__ out)
{
    __shared__ float t[32][33];
    in  += (long long)blockIdx.z * SEQ * DIM;
    out += (long long)blockIdx.z * DIM * SEQ;
    int r0 = blockIdx.y * 32, c0 = blockIdx.x * 32;
    int tx = threadIdx.x, ty = threadIdx.y;
#pragma unroll
    for (int i = 0; i < 4; i++)
        t[ty + i * 8][tx] = in[(long long)(r0 + ty + i * 8) * DIM + c0 + tx];
    __syncthreads();
#pragma unroll
    for (int i = 0; i < 4; i++) {
        int oc = ty + i * 8;
        out[(long long)(c0 + oc) * SEQ + r0 + tx] = t[tx][oc];
    }
}

__global__ void pack_bias(const float* __restrict__ b0, const float* __restrict__ b1,
                          const float* __restrict__ b2, float* __restrict__ dst)
{
    int t = threadIdx.x + blockIdx.x * 1024;
    const float* s = (blockIdx.x == 0) ? b0 : (blockIdx.x == 1) ? b1 : b2;
    dst[t] = s[threadIdx.x];
}

// ---------------------------------------------------------------------------
// Row softmax (rows of 2048), 256 threads, warp-shuffle reduce, tf32 out.
// ---------------------------------------------------------------------------
__global__ __launch_bounds__(256)
void softmax_rows(float* __restrict__ S)
{
    float4* row4 = reinterpret_cast<float4*>(S + (long long)blockIdx.x * SEQ);
    __shared__ float red[8];
    const int t = threadIdx.x;
    const int wid = t >> 5, lane = t & 31;

    float4 a = row4[t];
    float4 b = row4[t + 256];
    float mx = fmaxf(fmaxf(fmaxf(a.x, a.y), fmaxf(a.z, a.w)),
                     fmaxf(fmaxf(b.x, b.y), fmaxf(b.z, b.w)));
#pragma unroll
    for (int s = 16; s > 0; s >>= 1)
        mx = fmaxf(mx, __shfl_xor_sync(0xffffffffu, mx, s));
    if (lane == 0) red[wid] = mx;
    __syncthreads();
    mx = red[0];
#pragma unroll
    for (int i = 1; i < 8; i++) mx = fmaxf(mx, red[i]);

    a.x = __expf(a.x - mx); a.y = __expf(a.y - mx);
    a.z = __expf(a.z - mx); a.w = __expf(a.w - mx);
    b.x = __expf(b.x - mx); b.y = __expf(b.y - mx);
    b.z = __expf(b.z - mx); b.w = __expf(b.w - mx);
    float sum = (a.x + a.y) + (a.z + a.w) + (b.x + b.y) + (b.z + b.w);
#pragma unroll
    for (int s = 16; s > 0; s >>= 1)
        sum += __shfl_xor_sync(0xffffffffu, sum, s);
    __syncthreads();
    if (lane == 0) red[wid] = sum;
    __syncthreads();
    sum = red[0];
#pragma unroll
    for (int i = 1; i < 8; i++) sum += red[i];
    float inv = 1.0f / sum;

    a.x = round_tf32(a.x * inv); a.y = round_tf32(a.y * inv);
    a.z = round_tf32(a.z * inv); a.w = round_tf32(a.w * inv);
    b.x = round_tf32(b.x * inv); b.y = round_tf32(b.y * inv);
    b.z = round_tf32(b.z * inv); b.w = round_tf32(b.w * inv);
    row4[t] = a;
    row4[t + 256] = b;
}

// ---------------------------------------------------------------------------
extern "C" void kernel_launch(void* const* d_in, const int* in_sizes, int n_in,
                              void* d_out, int out_size)
{
    const float* x  = (const float*)d_in[0];
    const float* Wq = (const float*)d_in[1];
    const float* bq = (const float*)d_in[2];
    const float* Wk = (const float*)d_in[3];
    const float* bk = (const float*)d_in[4];
    const float* Wv = (const float*)d_in[5];
    const float* bv = (const float*)d_in[6];
    float* out = (float*)d_out;

    static float *pQ = nullptr, *pK = nullptr, *pV = nullptr, *pS = nullptr,
                 *pxr = nullptr, *pWt = nullptr, *pb = nullptr;
    static cudaStream_t st[3];
    static cudaEvent_t eFork, eW, eB, eQKV, eV, eD[3];
    if (!pQ) {
        cudaGetSymbolAddress((void**)&pQ,  g_Q);
        cudaGetSymbolAddress((void**)&pK,  g_K);
        cudaGetSymbolAddress((void**)&pV,  g_V);
        cudaGetSymbolAddress((void**)&pS,  g_S);
        cudaGetSymbolAddress((void**)&pxr, g_xr);
        cudaGetSymbolAddress((void**)&pWt, g_Wt);
        cudaGetSymbolAddress((void**)&pb,  g_b);
        cudaFuncSetAttribute(gemm_nt<3>, cudaFuncAttributeMaxDynamicSharedMemorySize, GSMEM);
        cudaFuncSetAttribute(gemm_nt<1>, cudaFuncAttributeMaxDynamicSharedMemorySize, GSMEM);
        cudaFuncSetAttribute(gemm_nt<2>, cudaFuncAttributeMaxDynamicSharedMemorySize, GSMEM);
        for (int i = 0; i < 3; i++)
            cudaStreamCreateWithFlags(&st[i], cudaStreamNonBlocking);
        cudaEventCreateWithFlags(&eFork, cudaEventDisableTiming);
        cudaEventCreateWithFlags(&eW,    cudaEventDisableTiming);
        cudaEventCreateWithFlags(&eB,    cudaEventDisableTiming);
        cudaEventCreateWithFlags(&eQKV,  cudaEventDisableTiming);
        cudaEventCreateWithFlags(&eV,    cudaEventDisableTiming);
        for (int i = 0; i < 3; i++)
            cudaEventCreateWithFlags(&eD[i], cudaEventDisableTiming);
    }

    const int M = BATCH * SEQ;          // 8192
    const float scale = 0.03125f;       // 1/sqrt(1024)
    dim3 tb(32, 8);
    const long long sQ = (long long)SEQ * DIM;      // per-batch Q/K/V/out stride
    const long long sS = (long long)SEQ * SEQ;      // per-batch scores stride

    // ---- fork: pre-passes in parallel -------------------------------------
    cudaEventRecord(eFork, 0);
    cudaStreamWaitEvent(st[0], eFork, 0);
    cudaStreamWaitEvent(st[1], eFork, 0);

    round_pass<<<M * DIM / 1024, 256>>>(x, pxr);                    // stream 0
    transp_w3<<<dim3(32, 32, 3), tb, 0, st[0]>>>(Wq, Wk, Wv, pWt);  // st0
    cudaEventRecord(eW, st[0]);
    pack_bias<<<3, 1024, 0, st[1]>>>(bq, bk, bv, pb);               // st1
    cudaEventRecord(eB, st[1]);

    // ---- QKV on stream 0 (waits on W^T and bias) --------------------------
    cudaStreamWaitEvent(0, eW, 0);
    cudaStreamWaitEvent(0, eB, 0);
    gemm_nt<3><<<dim3(3072 / TN, M / TM, 1), 128, GSMEM>>>(
        pxr, pWt, pb, pQ, pK, pV, M, 3072, DIM, DIM, 0, 0, 0, 1.f);
    cudaEventRecord(eQKV, 0);

    // ---- V^T on st0 (overlaps the first score batches) --------------------
    cudaStreamWaitEvent(st[0], eQKV, 0);
    transp_v<<<dim3(32, 64, BATCH), tb, 0, st[0]>>>(pV, pxr);
    cudaEventRecord(eV, st[0]);

    // ---- per-batch score -> softmax -> PV pipeline ------------------------
    // batch 0 on stream 0; batches 1..3 on st[0..2]
    for (int b = 0; b < BATCH; b++) {
        cudaStream_t sb = (b == 0) ? (cudaStream_t)0 : st[b - 1];
        if (b >= 2) cudaStreamWaitEvent(sb, eQKV, 0);   // st[1],st[2] need QKV
        // (b==1 runs on st[0] after transp_v which already waited on eQKV)
        gemm_nt<1><<<dim3(SEQ / TN, SEQ / TM, 1), 128, GSMEM, sb>>>(
            pQ + b * sQ, pK + b * sQ, nullptr, pS + b * sS, nullptr, nullptr,
            SEQ, SEQ, DIM, SEQ, 0, 0, 0, scale);
        softmax_rows<<<SEQ, 256, 0, sb>>>(pS + b * sS);
        if (b != 1) cudaStreamWaitEvent(sb, eV, 0);     // PV needs V^T
        gemm_nt<2><<<dim3(DIM / TN, SEQ / TM, 1), 128, GSMEM, sb>>>(
            pS + b * sS, pxr + b * sQ, nullptr, out + b * sQ, nullptr, nullptr,
            SEQ, DIM, SEQ, DIM, 0, 0, 0, 1.f);
        if (b > 0) cudaEventRecord(eD[b - 1], sb);
    }

    // ---- join everything back to stream 0 ---------------------------------
    for (int i = 0; i < 3; i++)
        cudaStreamWaitEvent(0, eD[i], 0);
}

// round 13
// speedup vs baseline: 1.2216x; 1.0475x over previous
#include <cuda_runtime.h>
#include <cuda_bf16.h>
#include <cstdint>
#include <math.h>

// ===========================================================================
// out = softmax((xWq+bq)(xWk+bk)^T / 32) (xWv+bv);  B=4, S=2048, D=H=1024
// tf32 mma.sync GEMMs (128x128 CTA tiles, 128 thr, 2 CTAs/SM, 64x64 warp
// tiles, A+B fragment ping-pong, XOR-swizzled tiles).
// This round: 4 fully independent per-batch chains on 4 streams —
// round(x_b) -> QKV_b -> V^T_b -> score_b -> softmax_b -> PV_b.
// GPU saturated end-to-end; all tails/softmax hidden by sibling chains.
// ===========================================================================

#define BATCH 4
#define SEQ   2048
#define DIM   1024

__device__ float g_Q [BATCH * SEQ * DIM];
__device__ float g_K [BATCH * SEQ * DIM];
__device__ float g_V [BATCH * SEQ * DIM];
__device__ float g_S [BATCH * SEQ * SEQ];
__device__ float g_xr[BATCH * SEQ * DIM];    // x_b rounded; later V^T_b
__device__ float g_Wt[3 * DIM * DIM];        // packed W^T: rows n(3072), cols k(1024)
__device__ float g_b [3 * DIM];              // packed bq|bk|bv

// ---------------- helpers ---------------------------------------------------
__device__ __forceinline__ uint32_t smem_u32(const void* p) {
    uint32_t a;
    asm("{ .reg .u64 t; cvta.to.shared.u64 t, %1; cvt.u32.u64 %0, t; }"
        : "=r"(a) : "l"(p));
    return a;
}
__device__ __forceinline__ void cp16(uint32_t saddr, const void* g) {
    asm volatile("cp.async.cg.shared.global [%0], [%1], 16;" :: "r"(saddr), "l"(g));
}
__device__ __forceinline__ float round_tf32(float x) {
    uint32_t r;
    asm("cvt.rna.tf32.f32 %0, %1;" : "=r"(r) : "f"(x));
    return __uint_as_float(r);
}
__device__ __forceinline__ void mma_tf32(float* c, const uint32_t* a, const uint32_t* b) {
    asm volatile(
        "mma.sync.aligned.m16n8k8.row.col.f32.tf32.tf32.f32 "
        "{%0,%1,%2,%3}, {%4,%5,%6,%7}, {%8,%9}, {%0,%1,%2,%3};"
        : "+f"(c[0]), "+f"(c[1]), "+f"(c[2]), "+f"(c[3])
        : "r"(a[0]), "r"(a[1]), "r"(a[2]), "r"(a[3]), "r"(b[0]), "r"(b[1]));
}

// ===========================================================================
// NT GEMM: C[M,N] = A[M,K] x B[N,K]^T, 128x128xKB32 CTA tiles, 128 threads,
// 4 warps as 2x2 with 64x64 warp tiles. 3-stage cp.async, XOR-swizzled
// 128B-row tiles, A+B fragments double-buffered across kk (ping-pong).
// MODE: 1 = *alpha, 2 = plain, 3 = fused QKV (+packed bias, tf32 round,
//       route to C0/C1/C2 by n0>>10)
// ===========================================================================
#define TM 128
#define TN 128
#define KB 32
#define ASTRIDE (TM * 32)
#define BSTRIDE (TN * 32)
#define GSMEM   (3 * (ASTRIDE + BSTRIDE) * 4)   // 98304 B

template <int MODE>
__global__ __launch_bounds__(128, 2)
void gemm_nt(const float* __restrict__ A, const float* __restrict__ B,
             const float* __restrict__ bias,
             float* __restrict__ C0, float* __restrict__ C1, float* __restrict__ C2,
             int M, int N, int K, int ldc, float alpha)
{
    extern __shared__ float sm[];
    const int tid  = threadIdx.x;
    const int wid  = tid >> 5;
    const int lane = tid & 31;
    const int gq = lane >> 2;
    const int tq = lane & 3;
    const int wm = (wid >> 1) * 64;     // 2x2 warp grid, 64x64 warp tiles
    const int wn = (wid & 1) * 64;
    const int axk = (gq & 3) << 2;

    const int m0 = blockIdx.y * TM;
    const int n0 = blockIdx.x * TN;

    float* As = sm;
    float* Bs = sm + 3 * ASTRIDE;

    auto loadA = [&](int k0, int s) {
        float* dst = As + s * ASTRIDE;
        const float* src = A + (long long)m0 * K + k0;
#pragma unroll
        for (int j = 0; j < 8; j++) {
            int idx = j * 128 + tid;
            int r = idx >> 3, ch = idx & 7;
            int off = r * 32 + (((2 * ch) ^ ((r & 3) << 2)) << 1);
            cp16(smem_u32(dst + off), src + (long long)r * K + ch * 4);
        }
    };
    auto loadB = [&](int k0, int s) {
        float* dst = Bs + s * BSTRIDE;
        const float* src = B + (long long)n0 * K + k0;
#pragma unroll
        for (int j = 0; j < 8; j++) {
            int idx = j * 128 + tid;
            int r = idx >> 3, ch = idx & 7;
            int off = r * 32 + (((2 * ch) ^ ((r & 3) << 2)) << 1);
            cp16(smem_u32(dst + off), src + (long long)r * K + ch * 4);
        }
    };

    float acc[4][8][4] = {};

    const int nIter = K / KB;
    loadA(0, 0); loadB(0, 0);
    asm volatile("cp.async.commit_group;" ::: "memory");
    loadA(KB, 1); loadB(KB, 1);
    asm volatile("cp.async.commit_group;" ::: "memory");

    for (int it = 0; it < nIter; it++) {
        asm volatile("cp.async.wait_group 1;" ::: "memory");
        __syncthreads();

        if (it + 2 < nIter) {
            loadA((it + 2) * KB, (it + 2) % 3);
            loadB((it + 2) * KB, (it + 2) % 3);
        }
        asm volatile("cp.async.commit_group;" ::: "memory");

        const float* a_s = As + (it % 3) * ASTRIDE;
        const float* b_s = Bs + (it % 3) * BSTRIDE;

        uint32_t af[2][4][4];
        uint32_t bf[2][8][2];
        auto ldfrag = [&](int kk, uint32_t (&afx)[4][4], uint32_t (&bfx)[8][2]) {
            const int cA = (((kk << 2) + tq) ^ axk) << 1;
#pragma unroll
            for (int i = 0; i < 4; i++) {
                const float* ap = a_s + (wm + i * 16 + gq) * 32 + cA;
                uint2 u0 = *reinterpret_cast<const uint2*>(ap);
                uint2 u1 = *reinterpret_cast<const uint2*>(ap + 8 * 32);
                afx[i][0] = u0.x; afx[i][1] = u1.x;
                afx[i][2] = u0.y; afx[i][3] = u1.y;
            }
#pragma unroll
            for (int j = 0; j < 8; j++) {
                const float* bp = b_s + (wn + j * 8 + gq) * 32 + cA;
                uint2 v = *reinterpret_cast<const uint2*>(bp);
                bfx[j][0] = v.x; bfx[j][1] = v.y;
            }
        };

        ldfrag(0, af[0], bf[0]);
#pragma unroll
        for (int kk = 0; kk < 4; kk++) {
            if (kk < 3) ldfrag(kk + 1, af[(kk + 1) & 1], bf[(kk + 1) & 1]);
#pragma unroll
            for (int i = 0; i < 4; i++)
#pragma unroll
                for (int j = 0; j < 8; j++)
                    mma_tf32(acc[i][j], af[kk & 1][i], bf[kk & 1][j]);
        }
    }

    // epilogue
    float* Cw;
    int cshift = 0;
    if (MODE == 3) {
        const int mat = n0 >> 10;
        Cw = (mat == 0) ? C0 : (mat == 1) ? C1 : C2;
        cshift = n0 & ~1023;
    } else {
        Cw = C0;
    }
#pragma unroll
    for (int i = 0; i < 4; i++) {
#pragma unroll
        for (int j = 0; j < 8; j++) {
            const int r = m0 + wm + i * 16 + gq;
            const int c = n0 + wn + j * 8 + 2 * tq;
            float2 v0 = make_float2(acc[i][j][0], acc[i][j][1]);
            float2 v1 = make_float2(acc[i][j][2], acc[i][j][3]);
            if (MODE == 3) {
                float2 bz2 = *reinterpret_cast<const float2*>(bias + c);
                v0.x = round_tf32(v0.x + bz2.x);
                v0.y = round_tf32(v0.y + bz2.y);
                v1.x = round_tf32(v1.x + bz2.x);
                v1.y = round_tf32(v1.y + bz2.y);
            }
            if (MODE == 1) {
                v0.x *= alpha; v0.y *= alpha;
                v1.x *= alpha; v1.y *= alpha;
            }
            const int cc = c - cshift;
            *reinterpret_cast<float2*>(Cw + (long long)r * ldc + cc) = v0;
            *reinterpret_cast<float2*>(Cw + (long long)(r + 8) * ldc + cc) = v1;
        }
    }
}

// ---------------------------------------------------------------------------
// tf32 rounding + transpose utilities
// ---------------------------------------------------------------------------
__global__ __launch_bounds__(256)
void round_pass(const float* __restrict__ src, float* __restrict__ dst)
{
    int idx = blockIdx.x * 256 + threadIdx.x;
    float4 v = reinterpret_cast<const float4*>(src)[idx];
    v.x = round_tf32(v.x); v.y = round_tf32(v.y);
    v.z = round_tf32(v.z); v.w = round_tf32(v.w);
    reinterpret_cast<float4*>(dst)[idx] = v;
}

__global__ void transp_w3(const float* __restrict__ w0, const float* __restrict__ w1,
                          const float* __restrict__ w2, float* __restrict__ out)
{
    __shared__ float t[32][33];
    const float* in = (blockIdx.z == 0) ? w0 : (blockIdx.z == 1) ? w1 : w2;
    float* o = out + (long long)blockIdx.z * DIM * DIM;
    int r0 = blockIdx.y * 32, c0 = blockIdx.x * 32;
    int tx = threadIdx.x, ty = threadIdx.y;
#pragma unroll
    for (int i = 0; i < 4; i++)
        t[ty + i * 8][tx] = in[(long long)(r0 + ty + i * 8) * DIM + c0 + tx];
    __syncthreads();
#pragma unroll
    for (int i = 0; i < 4; i++) {
        int oc = ty + i * 8;
        o[(long long)(c0 + oc) * DIM + r0 + tx] = round_tf32(t[tx][oc]);
    }
}

// transpose one batch of V: [2048,1024] -> [1024,2048]
__global__ void transp_v1(const float* __restrict__ in, float* __restrict__ out)
{
    __shared__ float t[32][33];
    int r0 = blockIdx.y * 32, c0 = blockIdx.x * 32;
    int tx = threadIdx.x, ty = threadIdx.y;
#pragma unroll
    for (int i = 0; i < 4; i++)
        t[ty + i * 8][tx] = in[(long long)(r0 + ty + i * 8) * DIM + c0 + tx];
    __syncthreads();
#pragma unroll
    for (int i = 0; i < 4; i++) {
        int oc = ty + i * 8;
        out[(long long)(c0 + oc) * SEQ + r0 + tx] = t[tx][oc];
    }
}

__global__ void pack_bias(const float* __restrict__ b0, const float* __restrict__ b1,
                          const float* __restrict__ b2, float* __restrict__ dst)
{
    int t = threadIdx.x + blockIdx.x * 1024;
    const float* s = (blockIdx.x == 0) ? b0 : (blockIdx.x == 1) ? b1 : b2;
    dst[t] = s[threadIdx.x];
}

// ---------------------------------------------------------------------------
// Row softmax (rows of 2048), 256 threads, warp-shuffle reduce, tf32 out.
// ---------------------------------------------------------------------------
__global__ __launch_bounds__(256)
void softmax_rows(float* __restrict__ S)
{
    float4* row4 = reinterpret_cast<float4*>(S + (long long)blockIdx.x * SEQ);
    __shared__ float red[8];
    const int t = threadIdx.x;
    const int wid = t >> 5, lane = t & 31;

    float4 a = row4[t];
    float4 b = row4[t + 256];
    float mx = fmaxf(fmaxf(fmaxf(a.x, a.y), fmaxf(a.z, a.w)),
                     fmaxf(fmaxf(b.x, b.y), fmaxf(b.z, b.w)));
#pragma unroll
    for (int s = 16; s > 0; s >>= 1)
        mx = fmaxf(mx, __shfl_xor_sync(0xffffffffu, mx, s));
    if (lane == 0) red[wid] = mx;
    __syncthreads();
    mx = red[0];
#pragma unroll
    for (int i = 1; i < 8; i++) mx = fmaxf(mx, red[i]);

    a.x = __expf(a.x - mx); a.y = __expf(a.y - mx);
    a.z = __expf(a.z - mx); a.w = __expf(a.w - mx);
    b.x = __expf(b.x - mx); b.y = __expf(b.y - mx);
    b.z = __expf(b.z - mx); b.w = __expf(b.w - mx);
    float sum = (a.x + a.y) + (a.z + a.w) + (b.x + b.y) + (b.z + b.w);
#pragma unroll
    for (int s = 16; s > 0; s >>= 1)
        sum += __shfl_xor_sync(0xffffffffu, sum, s);
    __syncthreads();
    if (lane == 0) red[wid] = sum;
    __syncthreads();
    sum = red[0];
#pragma unroll
    for (int i = 1; i < 8; i++) sum += red[i];
    float inv = 1.0f / sum;

    a.x = round_tf32(a.x * inv); a.y = round_tf32(a.y * inv);
    a.z = round_tf32(a.z * inv); a.w = round_tf32(a.w * inv);
    b.x = round_tf32(b.x * inv); b.y = round_tf32(b.y * inv);
    b.z = round_tf32(b.z * inv); b.w = round_tf32(b.w * inv);
    row4[t] = a;
    row4[t + 256] = b;
}

// ---------------------------------------------------------------------------
extern "C" void kernel_launch(void* const* d_in, const int* in_sizes, int n_in,
                              void* d_out, int out_size)
{
    const float* x  = (const float*)d_in[0];
    const float* Wq = (const float*)d_in[1];
    const float* bq = (const float*)d_in[2];
    const float* Wk = (const float*)d_in[3];
    const float* bk = (const float*)d_in[4];
    const float* Wv = (const float*)d_in[5];
    const float* bv = (const float*)d_in[6];
    float* out = (float*)d_out;

    static float *pQ = nullptr, *pK = nullptr, *pV = nullptr, *pS = nullptr,
                 *pxr = nullptr, *pWt = nullptr, *pb = nullptr;
    static cudaStream_t st[3];
    static cudaEvent_t ePre, eD[3];
    if (!pQ) {
        cudaGetSymbolAddress((void**)&pQ,  g_Q);
        cudaGetSymbolAddress((void**)&pK,  g_K);
        cudaGetSymbolAddress((void**)&pV,  g_V);
        cudaGetSymbolAddress((void**)&pS,  g_S);
        cudaGetSymbolAddress((void**)&pxr, g_xr);
        cudaGetSymbolAddress((void**)&pWt, g_Wt);
        cudaGetSymbolAddress((void**)&pb,  g_b);
        cudaFuncSetAttribute(gemm_nt<3>, cudaFuncAttributeMaxDynamicSharedMemorySize, GSMEM);
        cudaFuncSetAttribute(gemm_nt<1>, cudaFuncAttributeMaxDynamicSharedMemorySize, GSMEM);
        cudaFuncSetAttribute(gemm_nt<2>, cudaFuncAttributeMaxDynamicSharedMemorySize, GSMEM);
        for (int i = 0; i < 3; i++)
            cudaStreamCreateWithFlags(&st[i], cudaStreamNonBlocking);
        cudaEventCreateWithFlags(&ePre, cudaEventDisableTiming);
        for (int i = 0; i < 3; i++)
            cudaEventCreateWithFlags(&eD[i], cudaEventDisableTiming);
    }

    const float scale = 0.03125f;       // 1/sqrt(1024)
    dim3 tb(32, 8);
    const long long sQ = (long long)SEQ * DIM;      // per-batch Q/K/V/out stride
    const long long sS = (long long)SEQ * SEQ;      // per-batch scores stride

    // ---- shared prep on stream 0 (tiny): W^T + bias -----------------------
    transp_w3<<<dim3(32, 32, 3), tb>>>(Wq, Wk, Wv, pWt);
    pack_bias<<<3, 1024>>>(bq, bk, bv, pb);
    cudaEventRecord(ePre, 0);

    // ---- 4 independent per-batch chains -----------------------------------
    for (int b = 0; b < BATCH; b++) {
        cudaStream_t sb = (b == 0) ? (cudaStream_t)0 : st[b - 1];
        if (b > 0) cudaStreamWaitEvent(sb, ePre, 0);

        // x_b -> tf32
        round_pass<<<SEQ * DIM / 1024, 256, 0, sb>>>(x + b * sQ, pxr + b * sQ);

        // QKV_b: [2048,1024] x W^T[3072,1024] -> Q_b, K_b, V_b
        gemm_nt<3><<<dim3(3072 / TN, SEQ / TM, 1), 128, GSMEM, sb>>>(
            pxr + b * sQ, pWt, pb, pQ + b * sQ, pK + b * sQ, pV + b * sQ,
            SEQ, 3072, DIM, DIM, 1.f);

        // V^T_b into pxr_b (QKV_b finished reading it; in-stream order)
        transp_v1<<<dim3(32, 64, 1), tb, 0, sb>>>(pV + b * sQ, pxr + b * sQ);

        // score_b = Q_b K_b^T * scale
        gemm_nt<1><<<dim3(SEQ / TN, SEQ / TM, 1), 128, GSMEM, sb>>>(
            pQ + b * sQ, pK + b * sQ, nullptr, pS + b * sS, nullptr, nullptr,
            SEQ, SEQ, DIM, SEQ, scale);

        // softmax_b (tf32-rounded)
        softmax_rows<<<SEQ, 256, 0, sb>>>(pS + b * sS);

        // out_b = P_b (V^T_b)^T
        gemm_nt<2><<<dim3(DIM / TN, SEQ / TM, 1), 128, GSMEM, sb>>>(
            pS + b * sS, pxr + b * sQ, nullptr, out + b * sQ, nullptr, nullptr,
            SEQ, DIM, SEQ, DIM, 1.f);

        if (b > 0) cudaEventRecord(eD[b - 1], sb);
    }

    // ---- join back to stream 0 --------------------------------------------
    for (int i = 0; i < 3; i++)
        cudaStreamWaitEvent(0, eD[i], 0);
}

// round 14
// speedup vs baseline: 1.4337x; 1.1736x over previous
#include <cuda_runtime.h>
#include <cuda_fp16.h>
#include <cstdint>
#include <math.h>

// ===========================================================================
// out = softmax((xWq+bq)(xWk+bk)^T / 32) (xWv+bv);  B=4, S=2048, D=H=1024
// QKV + score GEMMs: tf32 mma.sync (128x128 CTA tiles, 128 thr, 2 CTAs/SM,
// 64x64 warp tiles, fragment ping-pong, XOR-swizzled tiles).
// PV GEMM: fp16 m16n8k16 (2x tensor rate) — P in [0,1], V ~N(0,1) keep the
// added rounding ~3e-4. Producers store fp16 with an in-group-of-16 k
// shuffle so GEMM fragments are single LDS.64 (exact storage permutation).
// 4 independent per-batch stream chains (R13 schedule).
// ===========================================================================

#define BATCH 4
#define SEQ   2048
#define DIM   1024

__device__ float  g_Q [BATCH * SEQ * DIM];
__device__ float  g_K [BATCH * SEQ * DIM];
__device__ float  g_V [BATCH * SEQ * DIM];
__device__ float  g_S [BATCH * SEQ * SEQ];
__device__ float  g_xr[BATCH * SEQ * DIM];   // x rounded to tf32
__device__ float  g_Wt[3 * DIM * DIM];       // packed W^T (tf32-rounded)
__device__ float  g_b [3 * DIM];             // packed bq|bk|bv
__device__ __half g_Ph[BATCH * SEQ * SEQ];   // P fp16 (k-shuffled)
__device__ __half g_Vh[BATCH * DIM * SEQ];   // V^T fp16 (k-shuffled)

// ---------------- helpers ---------------------------------------------------
__device__ __forceinline__ uint32_t smem_u32(const void* p) {
    uint32_t a;
    asm("{ .reg .u64 t; cvta.to.shared.u64 t, %1; cvt.u32.u64 %0, t; }"
        : "=r"(a) : "l"(p));
    return a;
}
__device__ __forceinline__ void cp16(uint32_t saddr, const void* g) {
    asm volatile("cp.async.cg.shared.global [%0], [%1], 16;" :: "r"(saddr), "l"(g));
}
__device__ __forceinline__ float round_tf32(float x) {
    uint32_t r;
    asm("cvt.rna.tf32.f32 %0, %1;" : "=r"(r) : "f"(x));
    return __uint_as_float(r);
}
__device__ __forceinline__ void mma_tf32(float* c, const uint32_t* a, const uint32_t* b) {
    asm volatile(
        "mma.sync.aligned.m16n8k8.row.col.f32.tf32.tf32.f32 "
        "{%0,%1,%2,%3}, {%4,%5,%6,%7}, {%8,%9}, {%0,%1,%2,%3};"
        : "+f"(c[0]), "+f"(c[1]), "+f"(c[2]), "+f"(c[3])
        : "r"(a[0]), "r"(a[1]), "r"(a[2]), "r"(a[3]), "r"(b[0]), "r"(b[1]));
}
__device__ __forceinline__ void mma_f16(float* c, const uint32_t* a, const uint32_t* b) {
    asm volatile(
        "mma.sync.aligned.m16n8k16.row.col.f32.f16.f16.f32 "
        "{%0,%1,%2,%3}, {%4,%5,%6,%7}, {%8,%9}, {%0,%1,%2,%3};"
        : "+f"(c[0]), "+f"(c[1]), "+f"(c[2]), "+f"(c[3])
        : "r"(a[0]), "r"(a[1]), "r"(a[2]), "r"(a[3]), "r"(b[0]), "r"(b[1]));
}
// storage shuffle within each group of 16 k: slot s -> position
__device__ __forceinline__ int kpos(int k) {
    int s = k & 15;
    return (k & ~15) + (((s & 7) >> 1) << 2) + ((s >> 3) << 1) + (s & 1);
}

// ===========================================================================
// tf32 NT GEMM (unchanged from R13): C[M,N] = A[M,K] x B[N,K]^T
// MODE: 1 = *alpha, 3 = fused QKV (+bias, tf32 round, route by n0>>10)
// ===========================================================================
#define TM 128
#define TN 128
#define KB 32
#define ASTRIDE (TM * 32)
#define BSTRIDE (TN * 32)
#define GSMEM   (3 * (ASTRIDE + BSTRIDE) * 4)   // 98304 B

template <int MODE>
__global__ __launch_bounds__(128, 2)
void gemm_nt(const float* __restrict__ A, const float* __restrict__ B,
             const float* __restrict__ bias,
             float* __restrict__ C0, float* __restrict__ C1, float* __restrict__ C2,
             int M, int N, int K, int ldc, float alpha)
{
    extern __shared__ float sm[];
    const int tid  = threadIdx.x;
    const int wid  = tid >> 5;
    const int lane = tid & 31;
    const int gq = lane >> 2;
    const int tq = lane & 3;
    const int wm = (wid >> 1) * 64;
    const int wn = (wid & 1) * 64;
    const int axk = (gq & 3) << 2;

    const int m0 = blockIdx.y * TM;
    const int n0 = blockIdx.x * TN;

    float* As = sm;
    float* Bs = sm + 3 * ASTRIDE;

    auto loadA = [&](int k0, int s) {
        float* dst = As + s * ASTRIDE;
        const float* src = A + (long long)m0 * K + k0;
#pragma unroll
        for (int j = 0; j < 8; j++) {
            int idx = j * 128 + tid;
            int r = idx >> 3, ch = idx & 7;
            int off = r * 32 + (((2 * ch) ^ ((r & 3) << 2)) << 1);
            cp16(smem_u32(dst + off), src + (long long)r * K + ch * 4);
        }
    };
    auto loadB = [&](int k0, int s) {
        float* dst = Bs + s * BSTRIDE;
        const float* src = B + (long long)n0 * K + k0;
#pragma unroll
        for (int j = 0; j < 8; j++) {
            int idx = j * 128 + tid;
            int r = idx >> 3, ch = idx & 7;
            int off = r * 32 + (((2 * ch) ^ ((r & 3) << 2)) << 1);
            cp16(smem_u32(dst + off), src + (long long)r * K + ch * 4);
        }
    };

    float acc[4][8][4] = {};

    const int nIter = K / KB;
    loadA(0, 0); loadB(0, 0);
    asm volatile("cp.async.commit_group;" ::: "memory");
    loadA(KB, 1); loadB(KB, 1);
    asm volatile("cp.async.commit_group;" ::: "memory");

    for (int it = 0; it < nIter; it++) {
        asm volatile("cp.async.wait_group 1;" ::: "memory");
        __syncthreads();

        if (it + 2 < nIter) {
            loadA((it + 2) * KB, (it + 2) % 3);
            loadB((it + 2) * KB, (it + 2) % 3);
        }
        asm volatile("cp.async.commit_group;" ::: "memory");

        const float* a_s = As + (it % 3) * ASTRIDE;
        const float* b_s = Bs + (it % 3) * BSTRIDE;

        uint32_t af[2][4][4];
        uint32_t bf[2][8][2];
        auto ldfrag = [&](int kk, uint32_t (&afx)[4][4], uint32_t (&bfx)[8][2]) {
            const int cA = (((kk << 2) + tq) ^ axk) << 1;
#pragma unroll
            for (int i = 0; i < 4; i++) {
                const float* ap = a_s + (wm + i * 16 + gq) * 32 + cA;
                uint2 u0 = *reinterpret_cast<const uint2*>(ap);
                uint2 u1 = *reinterpret_cast<const uint2*>(ap + 8 * 32);
                afx[i][0] = u0.x; afx[i][1] = u1.x;
                afx[i][2] = u0.y; afx[i][3] = u1.y;
            }
#pragma unroll
            for (int j = 0; j < 8; j++) {
                const float* bp = b_s + (wn + j * 8 + gq) * 32 + cA;
                uint2 v = *reinterpret_cast<const uint2*>(bp);
                bfx[j][0] = v.x; bfx[j][1] = v.y;
            }
        };

        ldfrag(0, af[0], bf[0]);
#pragma unroll
        for (int kk = 0; kk < 4; kk++) {
            if (kk < 3) ldfrag(kk + 1, af[(kk + 1) & 1], bf[(kk + 1) & 1]);
#pragma unroll
            for (int i = 0; i < 4; i++)
#pragma unroll
                for (int j = 0; j < 8; j++)
                    mma_tf32(acc[i][j], af[kk & 1][i], bf[kk & 1][j]);
        }
    }

    float* Cw;
    int cshift = 0;
    if (MODE == 3) {
        const int mat = n0 >> 10;
        Cw = (mat == 0) ? C0 : (mat == 1) ? C1 : C2;
        cshift = n0 & ~1023;
    } else {
        Cw = C0;
    }
#pragma unroll
    for (int i = 0; i < 4; i++) {
#pragma unroll
        for (int j = 0; j < 8; j++) {
            const int r = m0 + wm + i * 16 + gq;
            const int c = n0 + wn + j * 8 + 2 * tq;
            float2 v0 = make_float2(acc[i][j][0], acc[i][j][1]);
            float2 v1 = make_float2(acc[i][j][2], acc[i][j][3]);
            if (MODE == 3) {
                float2 bz2 = *reinterpret_cast<const float2*>(bias + c);
                v0.x = round_tf32(v0.x + bz2.x);
                v0.y = round_tf32(v0.y + bz2.y);
                v1.x = round_tf32(v1.x + bz2.x);
                v1.y = round_tf32(v1.y + bz2.y);
            }
            if (MODE == 1) {
                v0.x *= alpha; v0.y *= alpha;
                v1.x *= alpha; v1.y *= alpha;
            }
            const int cc = c - cshift;
            *reinterpret_cast<float2*>(Cw + (long long)r * ldc + cc) = v0;
            *reinterpret_cast<float2*>(Cw + (long long)(r + 8) * ldc + cc) = v1;
        }
    }
}

// ===========================================================================
// fp16 NT GEMM for PV: C[2048,1024] f32 = P[2048,2048] f16 x V^T[1024,2048]^T
// 128x128 CTA tiles, K-chunk 64 halves (128B rows, same XOR swizzle),
// m16n8k16 HMMA, operands stored k-shuffled so fragments are LDS.64.
// ===========================================================================
#define KH   64
#define AHB  16384                         // bytes per A/B stage (128 x 128B)
#define PVSM (3 * 2 * AHB)                 // 98304 B

__global__ __launch_bounds__(128, 2)
void gemm_pv(const __half* __restrict__ A, const __half* __restrict__ B,
             float* __restrict__ C, int M, int N, int K)
{
    extern __shared__ char smh[];
    const int tid  = threadIdx.x;
    const int wid  = tid >> 5;
    const int lane = tid & 31;
    const int gq = lane >> 2;
    const int tq = lane & 3;
    const int wm = (wid >> 1) * 64;
    const int wn = (wid & 1) * 64;
    const int axk = (gq & 3) << 2;

    const int m0 = blockIdx.y * TM;
    const int n0 = blockIdx.x * TN;

    char* As = smh;
    char* Bs = smh + 3 * AHB;

    auto loadT = [&](const __half* base, char* dstb, int rows0, int k0, int s) {
        char* dst = dstb + s * AHB;
        const char* src = (const char*)(base + (long long)rows0 * K + k0);
        const long long rstride = (long long)K * 2;
#pragma unroll
        for (int j = 0; j < 8; j++) {
            int idx = j * 128 + tid;
            int r = idx >> 3, ch = idx & 7;
            int off = r * 128 + (((2 * ch) ^ ((r & 3) << 2)) << 3);
            cp16(smem_u32(dst + off), src + r * rstride + ch * 16);
        }
    };

    float acc[4][8][4] = {};

    const int nIter = K / KH;              // 32
    loadT(A, As, m0, 0, 0); loadT(B, Bs, n0, 0, 0);
    asm volatile("cp.async.commit_group;" ::: "memory");
    loadT(A, As, m0, KH, 1); loadT(B, Bs, n0, KH, 1);
    asm volatile("cp.async.commit_group;" ::: "memory");

    for (int it = 0; it < nIter; it++) {
        asm volatile("cp.async.wait_group 1;" ::: "memory");
        __syncthreads();

        if (it + 2 < nIter) {
            loadT(A, As, m0, (it + 2) * KH, (it + 2) % 3);
            loadT(B, Bs, n0, (it + 2) * KH, (it + 2) % 3);
        }
        asm volatile("cp.async.commit_group;" ::: "memory");

        const char* a_s = As + (it % 3) * AHB;
        const char* b_s = Bs + (it % 3) * AHB;

        uint32_t af[2][4][4];
        uint32_t bf[2][8][2];
        auto ldfrag = [&](int kk, uint32_t (&afx)[4][4], uint32_t (&bfx)[8][2]) {
            const int off = ((((kk << 2) + tq) ^ axk) << 3);
#pragma unroll
            for (int i = 0; i < 4; i++) {
                const char* ap = a_s + (wm + i * 16 + gq) * 128 + off;
                uint2 lo = *reinterpret_cast<const uint2*>(ap);
                uint2 hi = *reinterpret_cast<const uint2*>(ap + 8 * 128);
                afx[i][0] = lo.x; afx[i][1] = hi.x;    // slots k=2tq..2tq+1
                afx[i][2] = lo.y; afx[i][3] = hi.y;    // slots k=2tq+8..2tq+9
            }
#pragma unroll
            for (int j = 0; j < 8; j++) {
                uint2 v = *reinterpret_cast<const uint2*>(
                    b_s + (wn + j * 8 + gq) * 128 + off);
                bfx[j][0] = v.x; bfx[j][1] = v.y;
            }
        };

        ldfrag(0, af[0], bf[0]);
#pragma unroll
        for (int kk = 0; kk < 4; kk++) {
            if (kk < 3) ldfrag(kk + 1, af[(kk + 1) & 1], bf[(kk + 1) & 1]);
#pragma unroll
            for (int i = 0; i < 4; i++)
#pragma unroll
                for (int j = 0; j < 8; j++)
                    mma_f16(acc[i][j], af[kk & 1][i], bf[kk & 1][j]);
        }
    }

#pragma unroll
    for (int i = 0; i < 4; i++) {
#pragma unroll
        for (int j = 0; j < 8; j++) {
            const int r = m0 + wm + i * 16 + gq;
            const int c = n0 + wn + j * 8 + 2 * tq;
            *reinterpret_cast<float2*>(C + (long long)r * N + c) =
                make_float2(acc[i][j][0], acc[i][j][1]);
            *reinterpret_cast<float2*>(C + (long long)(r + 8) * N + c) =
                make_float2(acc[i][j][2], acc[i][j][3]);
        }
    }
}

// ---------------------------------------------------------------------------
// pre/post utilities
// ---------------------------------------------------------------------------
__global__ __launch_bounds__(256)
void round_pass(const float* __restrict__ src, float* __restrict__ dst)
{
    int idx = blockIdx.x * 256 + threadIdx.x;
    float4 v = reinterpret_cast<const float4*>(src)[idx];
    v.x = round_tf32(v.x); v.y = round_tf32(v.y);
    v.z = round_tf32(v.z); v.w = round_tf32(v.w);
    reinterpret_cast<float4*>(dst)[idx] = v;
}

__global__ void transp_w3(const float* __restrict__ w0, const float* __restrict__ w1,
                          const float* __restrict__ w2, float* __restrict__ out)
{
    __shared__ float t[32][33];
    const float* in = (blockIdx.z == 0) ? w0 : (blockIdx.z == 1) ? w1 : w2;
    float* o = out + (long long)blockIdx.z * DIM * DIM;
    int r0 = blockIdx.y * 32, c0 = blockIdx.x * 32;
    int tx = threadIdx.x, ty = threadIdx.y;
#pragma unroll
    for (int i = 0; i < 4; i++)
        t[ty + i * 8][tx] = in[(long long)(r0 + ty + i * 8) * DIM + c0 + tx];
    __syncthreads();
#pragma unroll
    for (int i = 0; i < 4; i++) {
        int oc = ty + i * 8;
        o[(long long)(c0 + oc) * DIM + r0 + tx] = round_tf32(t[tx][oc]);
    }
}

// V_b [2048,1024] f32 -> V^T_b [1024,2048] f16, k-shuffled columns
__global__ void transp_v1h(const float* __restrict__ in, __half* __restrict__ out)
{
    __shared__ float t[32][33];
    int r0 = blockIdx.y * 32, c0 = blockIdx.x * 32;
    int tx = threadIdx.x, ty = threadIdx.y;
#pragma unroll
    for (int i = 0; i < 4; i++)
        t[ty + i * 8][tx] = in[(long long)(r0 + ty + i * 8) * DIM + c0 + tx];
    __syncthreads();
    int k = r0 + tx;                      // seq index = contraction k
    int p = kpos(k);
#pragma unroll
    for (int i = 0; i < 4; i++) {
        int h = c0 + ty + i * 8;
        out[(long long)h * SEQ + p] = __float2half(t[tx][ty + i * 8]);
    }
}

__global__ void pack_bias(const float* __restrict__ b0, const float* __restrict__ b1,
                          const float* __restrict__ b2, float* __restrict__ dst)
{
    int t = threadIdx.x + blockIdx.x * 1024;
    const float* s = (blockIdx.x == 0) ? b0 : (blockIdx.x == 1) ? b1 : b2;
    dst[t] = s[threadIdx.x];
}

// ---------------------------------------------------------------------------
// Row softmax: reads S (f32), writes P f16 k-shuffled. 256 thr/row.
// ---------------------------------------------------------------------------
__global__ __launch_bounds__(256)
void softmax_ph(const float* __restrict__ S, __half* __restrict__ Ph)
{
    const float4* row4 = reinterpret_cast<const float4*>(S + (long long)blockIdx.x * SEQ);
    __half* prow = Ph + (long long)blockIdx.x * SEQ;
    __shared__ float red[8];
    const int t = threadIdx.x;
    const int wid = t >> 5, lane = t & 31;

    float4 a = row4[t];
    float4 b = row4[t + 256];
    float mx = fmaxf(fmaxf(fmaxf(a.x, a.y), fmaxf(a.z, a.w)),
                     fmaxf(fmaxf(b.x, b.y), fmaxf(b.z, b.w)));
#pragma unroll
    for (int s = 16; s > 0; s >>= 1)
        mx = fmaxf(mx, __shfl_xor_sync(0xffffffffu, mx, s));
    if (lane == 0) red[wid] = mx;
    __syncthreads();
    mx = red[0];
#pragma unroll
    for (int i = 1; i < 8; i++) mx = fmaxf(mx, red[i]);

    a.x = __expf(a.x - mx); a.y = __expf(a.y - mx);
    a.z = __expf(a.z - mx); a.w = __expf(a.w - mx);
    b.x = __expf(b.x - mx); b.y = __expf(b.y - mx);
    b.z = __expf(b.z - mx); b.w = __expf(b.w - mx);
    float sum = (a.x + a.y) + (a.z + a.w) + (b.x + b.y) + (b.z + b.w);
#pragma unroll
    for (int s = 16; s > 0; s >>= 1)
        sum += __shfl_xor_sync(0xffffffffu, sum, s);
    __syncthreads();
    if (lane == 0) red[wid] = sum;
    __syncthreads();
    sum = red[0];
#pragma unroll
    for (int i = 1; i < 8; i++) sum += red[i];
    float inv = 1.0f / sum;

    // write fp16 pairs at shuffled positions (even k pairs stay contiguous)
    int c0 = 4 * t;
    *reinterpret_cast<__half2*>(prow + kpos(c0))     = __floats2half2_rn(a.x * inv, a.y * inv);
    *reinterpret_cast<__half2*>(prow + kpos(c0 + 2)) = __floats2half2_rn(a.z * inv, a.w * inv);
    int c1 = 1024 + 4 * t;
    *reinterpret_cast<__half2*>(prow + kpos(c1))     = __floats2half2_rn(b.x * inv, b.y * inv);
    *reinterpret_cast<__half2*>(prow + kpos(c1 + 2)) = __floats2half2_rn(b.z * inv, b.w * inv);
}

// ---------------------------------------------------------------------------
extern "C" void kernel_launch(void* const* d_in, const int* in_sizes, int n_in,
                              void* d_out, int out_size)
{
    const float* x  = (const float*)d_in[0];
    const float* Wq = (const float*)d_in[1];
    const float* bq = (const float*)d_in[2];
    const float* Wk = (const float*)d_in[3];
    const float* bk = (const float*)d_in[4];
    const float* Wv = (const float*)d_in[5];
    const float* bv = (const float*)d_in[6];
    float* out = (float*)d_out;

    static float *pQ = nullptr, *pK = nullptr, *pV = nullptr, *pS = nullptr,
                 *pxr = nullptr, *pWt = nullptr, *pb = nullptr;
    static __half *pPh = nullptr, *pVh = nullptr;
    static cudaStream_t st[3];
    static cudaEvent_t ePre, eD[3];
    if (!pQ) {
        cudaGetSymbolAddress((void**)&pQ,  g_Q);
        cudaGetSymbolAddress((void**)&pK,  g_K);
        cudaGetSymbolAddress((void**)&pV,  g_V);
        cudaGetSymbolAddress((void**)&pS,  g_S);
        cudaGetSymbolAddress((void**)&pxr, g_xr);
        cudaGetSymbolAddress((void**)&pWt, g_Wt);
        cudaGetSymbolAddress((void**)&pb,  g_b);
        cudaGetSymbolAddress((void**)&pPh, g_Ph);
        cudaGetSymbolAddress((void**)&pVh, g_Vh);
        cudaFuncSetAttribute(gemm_nt<3>, cudaFuncAttributeMaxDynamicSharedMemorySize, GSMEM);
        cudaFuncSetAttribute(gemm_nt<1>, cudaFuncAttributeMaxDynamicSharedMemorySize, GSMEM);
        cudaFuncSetAttribute(gemm_pv,    cudaFuncAttributeMaxDynamicSharedMemorySize, PVSM);
        for (int i = 0; i < 3; i++)
            cudaStreamCreateWithFlags(&st[i], cudaStreamNonBlocking);
        cudaEventCreateWithFlags(&ePre, cudaEventDisableTiming);
        for (int i = 0; i < 3; i++)
            cudaEventCreateWithFlags(&eD[i], cudaEventDisableTiming);
    }

    const float scale = 0.03125f;       // 1/sqrt(1024)
    dim3 tb(32, 8);
    const long long sQ = (long long)SEQ * DIM;
    const long long sS = (long long)SEQ * SEQ;

    // shared prep (tiny) on stream 0
    transp_w3<<<dim3(32, 32, 3), tb>>>(Wq, Wk, Wv, pWt);
    pack_bias<<<3, 1024>>>(bq, bk, bv, pb);
    cudaEventRecord(ePre, 0);

    // 4 independent per-batch chains
    for (int b = 0; b < BATCH; b++) {
        cudaStream_t sb = (b == 0) ? (cudaStream_t)0 : st[b - 1];
        if (b > 0) cudaStreamWaitEvent(sb, ePre, 0);

        round_pass<<<SEQ * DIM / 1024, 256, 0, sb>>>(x + b * sQ, pxr + b * sQ);

        gemm_nt<3><<<dim3(3072 / TN, SEQ / TM, 1), 128, GSMEM, sb>>>(
            pxr + b * sQ, pWt, pb, pQ + b * sQ, pK + b * sQ, pV + b * sQ,
            SEQ, 3072, DIM, DIM, 1.f);

        transp_v1h<<<dim3(32, 64, 1), tb, 0, sb>>>(pV + b * sQ, pVh + b * sQ);

        gemm_nt<1><<<dim3(SEQ / TN, SEQ / TM, 1), 128, GSMEM, sb>>>(
            pQ + b * sQ, pK + b * sQ, nullptr, pS + b * sS, nullptr, nullptr,
            SEQ, SEQ, DIM, SEQ, scale);

        softmax_ph<<<SEQ, 256, 0, sb>>>(pS + b * sS, pPh + b * sS);

        gemm_pv<<<dim3(DIM / TN, SEQ / TM, 1), 128, PVSM, sb>>>(
            pPh + b * sS, pVh + b * sQ, out + b * sQ, SEQ, DIM, SEQ);

        if (b > 0) cudaEventRecord(eD[b - 1], sb);
    }

    for (int i = 0; i < 3; i++)
        cudaStreamWaitEvent(0, eD[i], 0);
}

// round 15
// speedup vs baseline: 2.2650x; 1.5798x over previous
#include <cuda_runtime.h>
#include <cuda_fp16.h>
#include <cstdint>
#include <math.h>

// ===========================================================================
// out = softmax((xWq+bq)(xWk+bk)^T / 32) (xWv+bv);  B=4, S=2048, D=H=1024
// ALL GEMMs: fp16 m16n8k16 HMMA with f32 accumulate. fp16 has the SAME
// 10-bit mantissa as tf32 (verified R14: fp16 PV changed rel_err by 1e-8),
// at 2x the tensor rate. Operands stored fp16 with an in-group-of-16 k
// shuffle (kpos) so GEMM fragments are single LDS.64 from XOR-swizzled
// 128B-row SMEM tiles. 4 independent per-batch stream chains.
// ===========================================================================

#define BATCH 4
#define SEQ   2048
#define DIM   1024

__device__ __half g_xh[BATCH * SEQ * DIM];   // x fp16, k-shuffled (d)
__device__ __half g_Wt[3 * DIM * DIM];       // W^T fp16, k-shuffled (d)
__device__ float  g_b [3 * DIM];             // packed bq|bk|bv
__device__ __half g_Qh[BATCH * SEQ * DIM];   // Q fp16, k-shuffled (h)
__device__ __half g_Kh[BATCH * SEQ * DIM];   // K fp16, k-shuffled (h)
__device__ float  g_V [BATCH * SEQ * DIM];   // V f32
__device__ float  g_S [BATCH * SEQ * SEQ];   // scores f32
__device__ __half g_Ph[BATCH * SEQ * SEQ];   // P fp16, k-shuffled (seq)
__device__ __half g_Vh[BATCH * DIM * SEQ];   // V^T fp16, k-shuffled (seq)

// ---------------- helpers ---------------------------------------------------
__device__ __forceinline__ uint32_t smem_u32(const void* p) {
    uint32_t a;
    asm("{ .reg .u64 t; cvta.to.shared.u64 t, %1; cvt.u32.u64 %0, t; }"
        : "=r"(a) : "l"(p));
    return a;
}
__device__ __forceinline__ void cp16(uint32_t saddr, const void* g) {
    asm volatile("cp.async.cg.shared.global [%0], [%1], 16;" :: "r"(saddr), "l"(g));
}
__device__ __forceinline__ void mma_f16(float* c, const uint32_t* a, const uint32_t* b) {
    asm volatile(
        "mma.sync.aligned.m16n8k16.row.col.f32.f16.f16.f32 "
        "{%0,%1,%2,%3}, {%4,%5,%6,%7}, {%8,%9}, {%0,%1,%2,%3};"
        : "+f"(c[0]), "+f"(c[1]), "+f"(c[2]), "+f"(c[3])
        : "r"(a[0]), "r"(a[1]), "r"(a[2]), "r"(a[3]), "r"(b[0]), "r"(b[1]));
}
// storage shuffle within each group of 16 k: slot s -> position
__device__ __forceinline__ int kpos(int k) {
    int s = k & 15;
    return (k & ~15) + (((s & 7) >> 1) << 2) + ((s >> 3) << 1) + (s & 1);
}

// ===========================================================================
// fp16 NT GEMM: C[M,N] = A[M,K]h x B[N,K]h^T (f32 accum)
// 128x128 CTA tiles, 128 thr (2x2 warps, 64x64 warp tiles), K-chunk 64
// halves (128B rows, XOR swizzle), fragment ping-pong across kk.
// MODE: 1 = *alpha f32 out, 2 = plain f32 out,
//       3 = fused QKV: +bias; n0>>10 routes to Q(h, kpos), K(h, kpos), V(f32)
// ===========================================================================
#define TM 128
#define TN 128
#define KH  64
#define AHB 16384                          // bytes per A/B stage (128 x 128B)
#define HSM (3 * 2 * AHB)                  // 98304 B

template <int MODE>
__global__ __launch_bounds__(128, 2)
void gemm_h(const __half* __restrict__ A, const __half* __restrict__ B,
            const float* __restrict__ bias,
            __half* __restrict__ C0h, __half* __restrict__ C1h,
            float* __restrict__ Cf,
            int M, int N, int K, int ldc, float alpha)
{
    extern __shared__ char smh[];
    const int tid  = threadIdx.x;
    const int wid  = tid >> 5;
    const int lane = tid & 31;
    const int gq = lane >> 2;
    const int tq = lane & 3;
    const int wm = (wid >> 1) * 64;
    const int wn = (wid & 1) * 64;
    const int axk = (gq & 3) << 2;

    const int m0 = blockIdx.y * TM;
    const int n0 = blockIdx.x * TN;

    char* As = smh;
    char* Bs = smh + 3 * AHB;

    auto loadT = [&](const __half* base, char* dstb, int rows0, int k0, int s) {
        char* dst = dstb + s * AHB;
        const char* src = (const char*)(base + (long long)rows0 * K + k0);
        const long long rstride = (long long)K * 2;
#pragma unroll
        for (int j = 0; j < 8; j++) {
            int idx = j * 128 + tid;
            int r = idx >> 3, ch = idx & 7;
            int off = r * 128 + (((2 * ch) ^ ((r & 3) << 2)) << 3);
            cp16(smem_u32(dst + off), src + r * rstride + ch * 16);
        }
    };

    float acc[4][8][4] = {};

    const int nIter = K / KH;
    loadT(A, As, m0, 0, 0); loadT(B, Bs, n0, 0, 0);
    asm volatile("cp.async.commit_group;" ::: "memory");
    loadT(A, As, m0, KH, 1); loadT(B, Bs, n0, KH, 1);
    asm volatile("cp.async.commit_group;" ::: "memory");

    for (int it = 0; it < nIter; it++) {
        asm volatile("cp.async.wait_group 1;" ::: "memory");
        __syncthreads();

        if (it + 2 < nIter) {
            loadT(A, As, m0, (it + 2) * KH, (it + 2) % 3);
            loadT(B, Bs, n0, (it + 2) * KH, (it + 2) % 3);
        }
        asm volatile("cp.async.commit_group;" ::: "memory");

        const char* a_s = As + (it % 3) * AHB;
        const char* b_s = Bs + (it % 3) * AHB;

        uint32_t af[2][4][4];
        uint32_t bf[2][8][2];
        auto ldfrag = [&](int kk, uint32_t (&afx)[4][4], uint32_t (&bfx)[8][2]) {
            const int off = ((((kk << 2) + tq) ^ axk) << 3);
#pragma unroll
            for (int i = 0; i < 4; i++) {
                const char* ap = a_s + (wm + i * 16 + gq) * 128 + off;
                uint2 lo = *reinterpret_cast<const uint2*>(ap);
                uint2 hi = *reinterpret_cast<const uint2*>(ap + 8 * 128);
                afx[i][0] = lo.x; afx[i][1] = hi.x;
                afx[i][2] = lo.y; afx[i][3] = hi.y;
            }
#pragma unroll
            for (int j = 0; j < 8; j++) {
                uint2 v = *reinterpret_cast<const uint2*>(
                    b_s + (wn + j * 8 + gq) * 128 + off);
                bfx[j][0] = v.x; bfx[j][1] = v.y;
            }
        };

        ldfrag(0, af[0], bf[0]);
#pragma unroll
        for (int kk = 0; kk < 4; kk++) {
            if (kk < 3) ldfrag(kk + 1, af[(kk + 1) & 1], bf[(kk + 1) & 1]);
#pragma unroll
            for (int i = 0; i < 4; i++)
#pragma unroll
                for (int j = 0; j < 8; j++)
                    mma_f16(acc[i][j], af[kk & 1][i], bf[kk & 1][j]);
        }
    }

    // epilogue
    int mat = 0, cshift = 0;
    if (MODE == 3) {
        mat = n0 >> 10;                     // uniform per tile (TN divides 1024)
        cshift = n0 & ~1023;
    }
#pragma unroll
    for (int i = 0; i < 4; i++) {
#pragma unroll
        for (int j = 0; j < 8; j++) {
            const int r = m0 + wm + i * 16 + gq;
            const int c = n0 + wn + j * 8 + 2 * tq;
            float2 v0 = make_float2(acc[i][j][0], acc[i][j][1]);
            float2 v1 = make_float2(acc[i][j][2], acc[i][j][3]);
            if (MODE == 1) {
                v0.x *= alpha; v0.y *= alpha;
                v1.x *= alpha; v1.y *= alpha;
            }
            if (MODE == 3) {
                float2 bz = *reinterpret_cast<const float2*>(bias + c);
                v0.x += bz.x; v0.y += bz.y;
                v1.x += bz.x; v1.y += bz.y;
                const int cc = c - cshift;
                if (mat == 2) {
                    *reinterpret_cast<float2*>(Cf + (long long)r * ldc + cc) = v0;
                    *reinterpret_cast<float2*>(Cf + (long long)(r + 8) * ldc + cc) = v1;
                } else {
                    __half* H = (mat == 0) ? C0h : C1h;
                    const int p = kpos(cc);   // cc even -> kpos(cc)+1 = kpos(cc+1)
                    *reinterpret_cast<__half2*>(H + (long long)r * ldc + p) =
                        __floats2half2_rn(v0.x, v0.y);
                    *reinterpret_cast<__half2*>(H + (long long)(r + 8) * ldc + p) =
                        __floats2half2_rn(v1.x, v1.y);
                }
            } else {
                *reinterpret_cast<float2*>(Cf + (long long)r * ldc + c) = v0;
                *reinterpret_cast<float2*>(Cf + (long long)(r + 8) * ldc + c) = v1;
            }
        }
    }
}

// ---------------------------------------------------------------------------
// conversions
// ---------------------------------------------------------------------------
// x_b f32 [2048,1024] -> fp16 k-shuffled
__global__ __launch_bounds__(256)
void conv_xh(const float* __restrict__ src, __half* __restrict__ dst)
{
    int idx = blockIdx.x * 256 + threadIdx.x;       // groups of 4 floats
    int r = idx >> 8;
    int c0 = (idx & 255) * 4;
    float4 v = reinterpret_cast<const float4*>(src)[idx];
    __half* drow = dst + (long long)r * DIM;
    *reinterpret_cast<__half2*>(drow + kpos(c0))     = __floats2half2_rn(v.x, v.y);
    *reinterpret_cast<__half2*>(drow + kpos(c0 + 2)) = __floats2half2_rn(v.z, v.w);
}

// all three W [1024,1024] -> packed W^T fp16 [3072,1024], k-shuffled cols
__global__ void transp_w3h(const float* __restrict__ w0, const float* __restrict__ w1,
                           const float* __restrict__ w2, __half* __restrict__ out)
{
    __shared__ float t[32][33];
    const float* in = (blockIdx.z == 0) ? w0 : (blockIdx.z == 1) ? w1 : w2;
    __half* o = out + (long long)blockIdx.z * DIM * DIM;
    int r0 = blockIdx.y * 32, c0 = blockIdx.x * 32;
    int tx = threadIdx.x, ty = threadIdx.y;
#pragma unroll
    for (int i = 0; i < 4; i++)
        t[ty + i * 8][tx] = in[(long long)(r0 + ty + i * 8) * DIM + c0 + tx];
    __syncthreads();
    int p = kpos(r0 + tx);                 // k = original row index
#pragma unroll
    for (int i = 0; i < 4; i++) {
        int oc = ty + i * 8;
        o[(long long)(c0 + oc) * DIM + p] = __float2half(t[tx][oc]);
    }
}

// V_b [2048,1024] f32 -> V^T_b [1024,2048] fp16, k-shuffled (k = seq)
__global__ void transp_v1h(const float* __restrict__ in, __half* __restrict__ out)
{
    __shared__ float t[32][33];
    int r0 = blockIdx.y * 32, c0 = blockIdx.x * 32;
    int tx = threadIdx.x, ty = threadIdx.y;
#pragma unroll
    for (int i = 0; i < 4; i++)
        t[ty + i * 8][tx] = in[(long long)(r0 + ty + i * 8) * DIM + c0 + tx];
    __syncthreads();
    int p = kpos(r0 + tx);                 // k = seq index
#pragma unroll
    for (int i = 0; i < 4; i++) {
        int h = c0 + ty + i * 8;
        out[(long long)h * SEQ + p] = __float2half(t[tx][ty + i * 8]);
    }
}

__global__ void pack_bias(const float* __restrict__ b0, const float* __restrict__ b1,
                          const float* __restrict__ b2, float* __restrict__ dst)
{
    int t = threadIdx.x + blockIdx.x * 1024;
    const float* s = (blockIdx.x == 0) ? b0 : (blockIdx.x == 1) ? b1 : b2;
    dst[t] = s[threadIdx.x];
}

// ---------------------------------------------------------------------------
// Row softmax: reads S f32, writes P fp16 k-shuffled (k = seq). 256 thr/row.
// ---------------------------------------------------------------------------
__global__ __launch_bounds__(256)
void softmax_ph(const float* __restrict__ S, __half* __restrict__ Ph)
{
    const float4* row4 = reinterpret_cast<const float4*>(S + (long long)blockIdx.x * SEQ);
    __half* prow = Ph + (long long)blockIdx.x * SEQ;
    __shared__ float red[8];
    const int t = threadIdx.x;
    const int wid = t >> 5, lane = t & 31;

    float4 a = row4[t];
    float4 b = row4[t + 256];
    float mx = fmaxf(fmaxf(fmaxf(a.x, a.y), fmaxf(a.z, a.w)),
                     fmaxf(fmaxf(b.x, b.y), fmaxf(b.z, b.w)));
#pragma unroll
    for (int s = 16; s > 0; s >>= 1)
        mx = fmaxf(mx, __shfl_xor_sync(0xffffffffu, mx, s));
    if (lane == 0) red[wid] = mx;
    __syncthreads();
    mx = red[0];
#pragma unroll
    for (int i = 1; i < 8; i++) mx = fmaxf(mx, red[i]);

    a.x = __expf(a.x - mx); a.y = __expf(a.y - mx);
    a.z = __expf(a.z - mx); a.w = __expf(a.w - mx);
    b.x = __expf(b.x - mx); b.y = __expf(b.y - mx);
    b.z = __expf(b.z - mx); b.w = __expf(b.w - mx);
    float sum = (a.x + a.y) + (a.z + a.w) + (b.x + b.y) + (b.z + b.w);
#pragma unroll
    for (int s = 16; s > 0; s >>= 1)
        sum += __shfl_xor_sync(0xffffffffu, sum, s);
    __syncthreads();
    if (lane == 0) red[wid] = sum;
    __syncthreads();
    sum = red[0];
#pragma unroll
    for (int i = 1; i < 8; i++) sum += red[i];
    float inv = 1.0f / sum;

    int c0 = 4 * t;
    *reinterpret_cast<__half2*>(prow + kpos(c0))     = __floats2half2_rn(a.x * inv, a.y * inv);
    *reinterpret_cast<__half2*>(prow + kpos(c0 + 2)) = __floats2half2_rn(a.z * inv, a.w * inv);
    int c1 = 1024 + 4 * t;
    *reinterpret_cast<__half2*>(prow + kpos(c1))     = __floats2half2_rn(b.x * inv, b.y * inv);
    *reinterpret_cast<__half2*>(prow + kpos(c1 + 2)) = __floats2half2_rn(b.z * inv, b.w * inv);
}

// ---------------------------------------------------------------------------
extern "C" void kernel_launch(void* const* d_in, const int* in_sizes, int n_in,
                              void* d_out, int out_size)
{
    const float* x  = (const float*)d_in[0];
    const float* Wq = (const float*)d_in[1];
    const float* bq = (const float*)d_in[2];
    const float* Wk = (const float*)d_in[3];
    const float* bk = (const float*)d_in[4];
    const float* Wv = (const float*)d_in[5];
    const float* bv = (const float*)d_in[6];
    float* out = (float*)d_out;

    static __half *pxh = nullptr, *pWt = nullptr, *pQh = nullptr, *pKh = nullptr,
                  *pPh = nullptr, *pVh = nullptr;
    static float *pb = nullptr, *pV = nullptr, *pS = nullptr;
    static cudaStream_t st[3];
    static cudaEvent_t ePre, eD[3];
    if (!pxh) {
        cudaGetSymbolAddress((void**)&pxh, g_xh);
        cudaGetSymbolAddress((void**)&pWt, g_Wt);
        cudaGetSymbolAddress((void**)&pb,  g_b);
        cudaGetSymbolAddress((void**)&pQh, g_Qh);
        cudaGetSymbolAddress((void**)&pKh, g_Kh);
        cudaGetSymbolAddress((void**)&pV,  g_V);
        cudaGetSymbolAddress((void**)&pS,  g_S);
        cudaGetSymbolAddress((void**)&pPh, g_Ph);
        cudaGetSymbolAddress((void**)&pVh, g_Vh);
        cudaFuncSetAttribute(gemm_h<1>, cudaFuncAttributeMaxDynamicSharedMemorySize, HSM);
        cudaFuncSetAttribute(gemm_h<2>, cudaFuncAttributeMaxDynamicSharedMemorySize, HSM);
        cudaFuncSetAttribute(gemm_h<3>, cudaFuncAttributeMaxDynamicSharedMemorySize, HSM);
        for (int i = 0; i < 3; i++)
            cudaStreamCreateWithFlags(&st[i], cudaStreamNonBlocking);
        cudaEventCreateWithFlags(&ePre, cudaEventDisableTiming);
        for (int i = 0; i < 3; i++)
            cudaEventCreateWithFlags(&eD[i], cudaEventDisableTiming);
    }

    const float scale = 0.03125f;       // 1/sqrt(1024)
    dim3 tb(32, 8);
    const long long sQ = (long long)SEQ * DIM;
    const long long sS = (long long)SEQ * SEQ;

    // shared prep (tiny) on stream 0
    transp_w3h<<<dim3(32, 32, 3), tb>>>(Wq, Wk, Wv, pWt);
    pack_bias<<<3, 1024>>>(bq, bk, bv, pb);
    cudaEventRecord(ePre, 0);

    // 4 independent per-batch chains
    for (int b = 0; b < BATCH; b++) {
        cudaStream_t sb = (b == 0) ? (cudaStream_t)0 : st[b - 1];
        if (b > 0) cudaStreamWaitEvent(sb, ePre, 0);

        // x_b -> fp16 (k-shuffled)
        conv_xh<<<SEQ * DIM / 1024, 256, 0, sb>>>(x + b * sQ, pxh + b * sQ);

        // QKV_b: fp16 GEMM, routes Q/K fp16 + V f32
        gemm_h<3><<<dim3(3072 / TN, SEQ / TM, 1), 128, HSM, sb>>>(
            pxh + b * sQ, pWt, pb, pQh + b * sQ, pKh + b * sQ, pV + b * sQ,
            SEQ, 3072, DIM, DIM, 1.f);

        // V^T_b fp16 (k-shuffled over seq)
        transp_v1h<<<dim3(32, 64, 1), tb, 0, sb>>>(pV + b * sQ, pVh + b * sQ);

        // score_b = Q_b K_b^T * scale (fp16 GEMM, f32 out)
        gemm_h<1><<<dim3(SEQ / TN, SEQ / TM, 1), 128, HSM, sb>>>(
            pQh + b * sQ, pKh + b * sQ, nullptr, nullptr, nullptr, pS + b * sS,
            SEQ, SEQ, DIM, SEQ, scale);

        // softmax_b -> P fp16 (k-shuffled over seq)
        softmax_ph<<<SEQ, 256, 0, sb>>>(pS + b * sS, pPh + b * sS);

        // out_b = P_b V_b (fp16 GEMM, f32 out)
        gemm_h<2><<<dim3(DIM / TN, SEQ / TM, 1), 128, HSM, sb>>>(
            pPh + b * sS, pVh + b * sQ, nullptr, nullptr, nullptr, out + b * sQ,
            SEQ, DIM, SEQ, DIM, 1.f);

        if (b > 0) cudaEventRecord(eD[b - 1], sb);
    }

    for (int i = 0; i < 3; i++)
        cudaStreamWaitEvent(0, eD[i], 0);
}

// round 16
// speedup vs baseline: 2.2868x; 1.0096x over previous
#include <cuda_runtime.h>
#include <cuda_fp16.h>
#include <cstdint>
#include <math.h>

// ===========================================================================
// out = softmax((xWq+bq)(xWk+bk)^T / 32) (xWv+bv);  B=4, S=2048, D=H=1024
// ALL GEMMs: fp16 m16n8k16 HMMA, f32 accumulate (fp16 mantissa == tf32
// mantissa; validated R14/R15). kpos k-shuffle storage -> LDS.64 fragments
// from XOR-swizzled 128B-row SMEM tiles. 4 per-batch stream chains.
// This round: S and V stored fp16 (traffic cut), bias read direct.
// ===========================================================================

#define BATCH 4
#define SEQ   2048
#define DIM   1024

__device__ __half g_xh[BATCH * SEQ * DIM];   // x fp16, k-shuffled (d)
__device__ __half g_Wt[3 * DIM * DIM];       // W^T fp16, k-shuffled (d)
__device__ __half g_Qh[BATCH * SEQ * DIM];   // Q fp16, k-shuffled (h)
__device__ __half g_Kh[BATCH * SEQ * DIM];   // K fp16, k-shuffled (h)
__device__ __half g_Vr[BATCH * SEQ * DIM];   // V fp16, row-major (plain)
__device__ __half g_Sh[BATCH * SEQ * SEQ];   // scores fp16 (plain)
__device__ __half g_Ph[BATCH * SEQ * SEQ];   // P fp16, k-shuffled (seq)
__device__ __half g_Vh[BATCH * DIM * SEQ];   // V^T fp16, k-shuffled (seq)

// ---------------- helpers ---------------------------------------------------
__device__ __forceinline__ uint32_t smem_u32(const void* p) {
    uint32_t a;
    asm("{ .reg .u64 t; cvta.to.shared.u64 t, %1; cvt.u32.u64 %0, t; }"
        : "=r"(a) : "l"(p));
    return a;
}
__device__ __forceinline__ void cp16(uint32_t saddr, const void* g) {
    asm volatile("cp.async.cg.shared.global [%0], [%1], 16;" :: "r"(saddr), "l"(g));
}
__device__ __forceinline__ void mma_f16(float* c, const uint32_t* a, const uint32_t* b) {
    asm volatile(
        "mma.sync.aligned.m16n8k16.row.col.f32.f16.f16.f32 "
        "{%0,%1,%2,%3}, {%4,%5,%6,%7}, {%8,%9}, {%0,%1,%2,%3};"
        : "+f"(c[0]), "+f"(c[1]), "+f"(c[2]), "+f"(c[3])
        : "r"(a[0]), "r"(a[1]), "r"(a[2]), "r"(a[3]), "r"(b[0]), "r"(b[1]));
}
// storage shuffle within each group of 16 k: slot s -> position
__device__ __forceinline__ int kpos(int k) {
    int s = k & 15;
    return (k & ~15) + (((s & 7) >> 1) << 2) + ((s >> 3) << 1) + (s & 1);
}

// ===========================================================================
// fp16 NT GEMM: C[M,N] = A[M,K]h x B[N,K]h^T (f32 accum)
// 128x128 CTA tiles, 128 thr (2x2 warps, 64x64 warp tiles), K-chunk 64
// halves (128B rows, XOR swizzle), fragment ping-pong across kk.
// MODE: 1 = score: *alpha, fp16 out (plain positions)
//       2 = PV:    f32 out
//       3 = QKV:   +bias (b0/b1/b2 by n0>>10); Q,K fp16 kpos; V fp16 plain
// ===========================================================================
#define TM 128
#define TN 128
#define KH  64
#define AHB 16384                          // bytes per A/B stage (128 x 128B)
#define HSM (3 * 2 * AHB)                  // 98304 B

template <int MODE>
__global__ __launch_bounds__(128, 2)
void gemm_h(const __half* __restrict__ A, const __half* __restrict__ B,
            const float* __restrict__ b0, const float* __restrict__ b1,
            const float* __restrict__ b2,
            __half* __restrict__ C0h, __half* __restrict__ C1h,
            __half* __restrict__ C2h, float* __restrict__ Cf,
            int M, int N, int K, int ldc, float alpha)
{
    extern __shared__ char smh[];
    const int tid  = threadIdx.x;
    const int wid  = tid >> 5;
    const int lane = tid & 31;
    const int gq = lane >> 2;
    const int tq = lane & 3;
    const int wm = (wid >> 1) * 64;
    const int wn = (wid & 1) * 64;
    const int axk = (gq & 3) << 2;

    const int m0 = blockIdx.y * TM;
    const int n0 = blockIdx.x * TN;

    char* As = smh;
    char* Bs = smh + 3 * AHB;

    auto loadT = [&](const __half* base, char* dstb, int rows0, int k0, int s) {
        char* dst = dstb + s * AHB;
        const char* src = (const char*)(base + (long long)rows0 * K + k0);
        const long long rstride = (long long)K * 2;
#pragma unroll
        for (int j = 0; j < 8; j++) {
            int idx = j * 128 + tid;
            int r = idx >> 3, ch = idx & 7;
            int off = r * 128 + (((2 * ch) ^ ((r & 3) << 2)) << 3);
            cp16(smem_u32(dst + off), src + r * rstride + ch * 16);
        }
    };

    float acc[4][8][4] = {};

    const int nIter = K / KH;
    loadT(A, As, m0, 0, 0); loadT(B, Bs, n0, 0, 0);
    asm volatile("cp.async.commit_group;" ::: "memory");
    loadT(A, As, m0, KH, 1); loadT(B, Bs, n0, KH, 1);
    asm volatile("cp.async.commit_group;" ::: "memory");

    for (int it = 0; it < nIter; it++) {
        asm volatile("cp.async.wait_group 1;" ::: "memory");
        __syncthreads();

        if (it + 2 < nIter) {
            loadT(A, As, m0, (it + 2) * KH, (it + 2) % 3);
            loadT(B, Bs, n0, (it + 2) * KH, (it + 2) % 3);
        }
        asm volatile("cp.async.commit_group;" ::: "memory");

        const char* a_s = As + (it % 3) * AHB;
        const char* b_s = Bs + (it % 3) * AHB;

        uint32_t af[2][4][4];
        uint32_t bf[2][8][2];
        auto ldfrag = [&](int kk, uint32_t (&afx)[4][4], uint32_t (&bfx)[8][2]) {
            const int off = ((((kk << 2) + tq) ^ axk) << 3);
#pragma unroll
            for (int i = 0; i < 4; i++) {
                const char* ap = a_s + (wm + i * 16 + gq) * 128 + off;
                uint2 lo = *reinterpret_cast<const uint2*>(ap);
                uint2 hi = *reinterpret_cast<const uint2*>(ap + 8 * 128);
                afx[i][0] = lo.x; afx[i][1] = hi.x;
                afx[i][2] = lo.y; afx[i][3] = hi.y;
            }
#pragma unroll
            for (int j = 0; j < 8; j++) {
                uint2 v = *reinterpret_cast<const uint2*>(
                    b_s + (wn + j * 8 + gq) * 128 + off);
                bfx[j][0] = v.x; bfx[j][1] = v.y;
            }
        };

        ldfrag(0, af[0], bf[0]);
#pragma unroll
        for (int kk = 0; kk < 4; kk++) {
            if (kk < 3) ldfrag(kk + 1, af[(kk + 1) & 1], bf[(kk + 1) & 1]);
#pragma unroll
            for (int i = 0; i < 4; i++)
#pragma unroll
                for (int j = 0; j < 8; j++)
                    mma_f16(acc[i][j], af[kk & 1][i], bf[kk & 1][j]);
        }
    }

    // epilogue
    int mat = 0, cshift = 0;
    const float* bias = nullptr;
    if (MODE == 3) {
        mat = n0 >> 10;                     // uniform per tile (TN divides 1024)
        cshift = n0 & ~1023;
        bias = (mat == 0) ? b0 : (mat == 1) ? b1 : b2;
    }
#pragma unroll
    for (int i = 0; i < 4; i++) {
#pragma unroll
        for (int j = 0; j < 8; j++) {
            const int r = m0 + wm + i * 16 + gq;
            const int c = n0 + wn + j * 8 + 2 * tq;
            float2 v0 = make_float2(acc[i][j][0], acc[i][j][1]);
            float2 v1 = make_float2(acc[i][j][2], acc[i][j][3]);
            if (MODE == 1) {
                // score: fp16 out at plain positions
                v0.x *= alpha; v0.y *= alpha;
                v1.x *= alpha; v1.y *= alpha;
                *reinterpret_cast<__half2*>(C0h + (long long)r * ldc + c) =
                    __floats2half2_rn(v0.x, v0.y);
                *reinterpret_cast<__half2*>(C0h + (long long)(r + 8) * ldc + c) =
                    __floats2half2_rn(v1.x, v1.y);
            } else if (MODE == 3) {
                const int cc = c - cshift;
                float2 bz = *reinterpret_cast<const float2*>(bias + cc);
                v0.x += bz.x; v0.y += bz.y;
                v1.x += bz.x; v1.y += bz.y;
                if (mat == 2) {
                    // V: fp16 plain (coalesced)
                    *reinterpret_cast<__half2*>(C2h + (long long)r * ldc + cc) =
                        __floats2half2_rn(v0.x, v0.y);
                    *reinterpret_cast<__half2*>(C2h + (long long)(r + 8) * ldc + cc) =
                        __floats2half2_rn(v1.x, v1.y);
                } else {
                    __half* H = (mat == 0) ? C0h : C1h;
                    const int p = kpos(cc);
                    *reinterpret_cast<__half2*>(H + (long long)r * ldc + p) =
                        __floats2half2_rn(v0.x, v0.y);
                    *reinterpret_cast<__half2*>(H + (long long)(r + 8) * ldc + p) =
                        __floats2half2_rn(v1.x, v1.y);
                }
            } else {
                *reinterpret_cast<float2*>(Cf + (long long)r * ldc + c) = v0;
                *reinterpret_cast<float2*>(Cf + (long long)(r + 8) * ldc + c) = v1;
            }
        }
    }
}

// ---------------------------------------------------------------------------
// conversions
// ---------------------------------------------------------------------------
// x_b f32 [2048,1024] -> fp16 k-shuffled
__global__ __launch_bounds__(256)
void conv_xh(const float* __restrict__ src, __half* __restrict__ dst)
{
    int idx = blockIdx.x * 256 + threadIdx.x;       // groups of 4 floats
    int r = idx >> 8;
    int c0 = (idx & 255) * 4;
    float4 v = reinterpret_cast<const float4*>(src)[idx];
    __half* drow = dst + (long long)r * DIM;
    *reinterpret_cast<__half2*>(drow + kpos(c0))     = __floats2half2_rn(v.x, v.y);
    *reinterpret_cast<__half2*>(drow + kpos(c0 + 2)) = __floats2half2_rn(v.z, v.w);
}

// all three W [1024,1024] -> packed W^T fp16 [3072,1024], k-shuffled cols
__global__ void transp_w3h(const float* __restrict__ w0, const float* __restrict__ w1,
                           const float* __restrict__ w2, __half* __restrict__ out)
{
    __shared__ float t[32][33];
    const float* in = (blockIdx.z == 0) ? w0 : (blockIdx.z == 1) ? w1 : w2;
    __half* o = out + (long long)blockIdx.z * DIM * DIM;
    int r0 = blockIdx.y * 32, c0 = blockIdx.x * 32;
    int tx = threadIdx.x, ty = threadIdx.y;
#pragma unroll
    for (int i = 0; i < 4; i++)
        t[ty + i * 8][tx] = in[(long long)(r0 + ty + i * 8) * DIM + c0 + tx];
    __syncthreads();
    int p = kpos(r0 + tx);                 // k = original row index
#pragma unroll
    for (int i = 0; i < 4; i++) {
        int oc = ty + i * 8;
        o[(long long)(c0 + oc) * DIM + p] = __float2half(t[tx][oc]);
    }
}

// V_b fp16 [2048,1024] -> V^T_b [1024,2048] fp16, k-shuffled (k = seq)
__global__ void transp_v1h(const __half* __restrict__ in, __half* __restrict__ out)
{
    __shared__ __half t[32][34];
    int r0 = blockIdx.y * 32, c0 = blockIdx.x * 32;
    int tx = threadIdx.x, ty = threadIdx.y;
#pragma unroll
    for (int i = 0; i < 4; i++)
        t[ty + i * 8][tx] = in[(long long)(r0 + ty + i * 8) * DIM + c0 + tx];
    __syncthreads();
    int p = kpos(r0 + tx);                 // k = seq index
#pragma unroll
    for (int i = 0; i < 4; i++) {
        int h = c0 + ty + i * 8;
        out[(long long)h * SEQ + p] = t[tx][ty + i * 8];
    }
}

// ---------------------------------------------------------------------------
// Row softmax: reads S fp16 (plain), writes P fp16 kpos-shuffled (k = seq).
// 256 thr/row; each thread handles 8 consecutive halves (one uint4 load).
// ---------------------------------------------------------------------------
__global__ __launch_bounds__(256)
void softmax_ph(const __half* __restrict__ S, __half* __restrict__ Ph)
{
    const uint4* row = reinterpret_cast<const uint4*>(S + (long long)blockIdx.x * SEQ);
    __half* prow = Ph + (long long)blockIdx.x * SEQ;
    __shared__ float red[8];
    const int t = threadIdx.x;
    const int wid = t >> 5, lane = t & 31;

    uint4 u = row[t];                       // halves 8t .. 8t+7
    const __half2* hp = reinterpret_cast<const __half2*>(&u);
    float e[8];
#pragma unroll
    for (int i = 0; i < 4; i++) {
        float2 f = __half22float2(hp[i]);
        e[2 * i] = f.x; e[2 * i + 1] = f.y;
    }

    float mx = e[0];
#pragma unroll
    for (int i = 1; i < 8; i++) mx = fmaxf(mx, e[i]);
#pragma unroll
    for (int s = 16; s > 0; s >>= 1)
        mx = fmaxf(mx, __shfl_xor_sync(0xffffffffu, mx, s));
    if (lane == 0) red[wid] = mx;
    __syncthreads();
    mx = red[0];
#pragma unroll
    for (int i = 1; i < 8; i++) mx = fmaxf(mx, red[i]);

    float sum = 0.f;
#pragma unroll
    for (int i = 0; i < 8; i++) {
        e[i] = __expf(e[i] - mx);
        sum += e[i];
    }
#pragma unroll
    for (int s = 16; s > 0; s >>= 1)
        sum += __shfl_xor_sync(0xffffffffu, sum, s);
    __syncthreads();
    if (lane == 0) red[wid] = sum;
    __syncthreads();
    sum = red[0];
#pragma unroll
    for (int i = 1; i < 8; i++) sum += red[i];
    float inv = 1.0f / sum;

    // kpos positions for halves 8t..8t+7: base + {0,4,8,12} + (t odd ? 2 : 0)
    const int base = (t >> 1) << 4;
    const int off  = (t & 1) << 1;
    *reinterpret_cast<__half2*>(prow + base + off)      = __floats2half2_rn(e[0] * inv, e[1] * inv);
    *reinterpret_cast<__half2*>(prow + base + off + 4)  = __floats2half2_rn(e[2] * inv, e[3] * inv);
    *reinterpret_cast<__half2*>(prow + base + off + 8)  = __floats2half2_rn(e[4] * inv, e[5] * inv);
    *reinterpret_cast<__half2*>(prow + base + off + 12) = __floats2half2_rn(e[6] * inv, e[7] * inv);
}

// ---------------------------------------------------------------------------
extern "C" void kernel_launch(void* const* d_in, const int* in_sizes, int n_in,
                              void* d_out, int out_size)
{
    const float* x  = (const float*)d_in[0];
    const float* Wq = (const float*)d_in[1];
    const float* bq = (const float*)d_in[2];
    const float* Wk = (const float*)d_in[3];
    const float* bk = (const float*)d_in[4];
    const float* Wv = (const float*)d_in[5];
    const float* bv = (const float*)d_in[6];
    float* out = (float*)d_out;

    static __half *pxh = nullptr, *pWt = nullptr, *pQh = nullptr, *pKh = nullptr,
                  *pVr = nullptr, *pSh = nullptr, *pPh = nullptr, *pVh = nullptr;
    static cudaStream_t st[3];
    static cudaEvent_t ePre, eD[3];
    if (!pxh) {
        cudaGetSymbolAddress((void**)&pxh, g_xh);
        cudaGetSymbolAddress((void**)&pWt, g_Wt);
        cudaGetSymbolAddress((void**)&pQh, g_Qh);
        cudaGetSymbolAddress((void**)&pKh, g_Kh);
        cudaGetSymbolAddress((void**)&pVr, g_Vr);
        cudaGetSymbolAddress((void**)&pSh, g_Sh);
        cudaGetSymbolAddress((void**)&pPh, g_Ph);
        cudaGetSymbolAddress((void**)&pVh, g_Vh);
        cudaFuncSetAttribute(gemm_h<1>, cudaFuncAttributeMaxDynamicSharedMemorySize, HSM);
        cudaFuncSetAttribute(gemm_h<2>, cudaFuncAttributeMaxDynamicSharedMemorySize, HSM);
        cudaFuncSetAttribute(gemm_h<3>, cudaFuncAttributeMaxDynamicSharedMemorySize, HSM);
        for (int i = 0; i < 3; i++)
            cudaStreamCreateWithFlags(&st[i], cudaStreamNonBlocking);
        cudaEventCreateWithFlags(&ePre, cudaEventDisableTiming);
        for (int i = 0; i < 3; i++)
            cudaEventCreateWithFlags(&eD[i], cudaEventDisableTiming);
    }

    const float scale = 0.03125f;       // 1/sqrt(1024)
    dim3 tb(32, 8);
    const long long sQ = (long long)SEQ * DIM;
    const long long sS = (long long)SEQ * SEQ;

    // shared prep (tiny) on stream 0
    transp_w3h<<<dim3(32, 32, 3), tb>>>(Wq, Wk, Wv, pWt);
    cudaEventRecord(ePre, 0);

    // 4 independent per-batch chains
    for (int b = 0; b < BATCH; b++) {
        cudaStream_t sb = (b == 0) ? (cudaStream_t)0 : st[b - 1];
        if (b > 0) cudaStreamWaitEvent(sb, ePre, 0);

        // x_b -> fp16 (k-shuffled)
        conv_xh<<<SEQ * DIM / 1024, 256, 0, sb>>>(x + b * sQ, pxh + b * sQ);

        // QKV_b: fp16 GEMM; Q/K fp16 kpos, V fp16 plain; bias direct
        gemm_h<3><<<dim3(3072 / TN, SEQ / TM, 1), 128, HSM, sb>>>(
            pxh + b * sQ, pWt, bq, bk, bv,
            pQh + b * sQ, pKh + b * sQ, pVr + b * sQ, nullptr,
            SEQ, 3072, DIM, DIM, 1.f);

        // V^T_b fp16 (k-shuffled over seq)
        transp_v1h<<<dim3(32, 64, 1), tb, 0, sb>>>(pVr + b * sQ, pVh + b * sQ);

        // score_b = Q_b K_b^T * scale -> fp16 S (plain)
        gemm_h<1><<<dim3(SEQ / TN, SEQ / TM, 1), 128, HSM, sb>>>(
            pQh + b * sQ, pKh + b * sQ, nullptr, nullptr, nullptr,
            pSh + b * sS, nullptr, nullptr, nullptr,
            SEQ, SEQ, DIM, SEQ, scale);

        // softmax_b -> P fp16 (k-shuffled over seq)
        softmax_ph<<<SEQ, 256, 0, sb>>>(pSh + b * sS, pPh + b * sS);

        // out_b = P_b V_b (fp16 GEMM, f32 out)
        gemm_h<2><<<dim3(DIM / TN, SEQ / TM, 1), 128, HSM, sb>>>(
            pPh + b * sS, pVh + b * sQ, nullptr, nullptr, nullptr,
            nullptr, nullptr, nullptr, out + b * sQ,
            SEQ, DIM, SEQ, DIM, 1.f);

        if (b > 0) cudaEventRecord(eD[b - 1], sb);
    }

    for (int i = 0; i < 3; i++)
        cudaStreamWaitEvent(0, eD[i], 0);
}